// round 12
// baseline (speedup 1.0000x reference)
#include <cuda_runtime.h>
#include <cuda_fp16.h>
#include <cstdint>
#include <math.h>

#define S_LEN   1024
#define D_MODEL 768
#define DI_     1536
#define N_ST    16
#define K_CONV  4
#define DTRANK  48
#define XDP     128
#define VOCAB   32000
#define NL_     2
#define NCHUNK  32
#define CLEN    32
#define GROUPS  (DI_ * N_ST)

// ---------------- scratch ----------------
__device__ __align__(128) float  g_x    [S_LEN * D_MODEL];
__device__ __align__(128) __half g_xh   [S_LEN * D_MODEL];
__device__ __align__(128) float  g_xz   [S_LEN * 2 * DI_];
__device__ __align__(128) __half g_xsh  [S_LEN * DI_];
__device__ __align__(128) __half g_xdblh[S_LEN * XDP];
__device__ __align__(128) float  g_dtl  [S_LEN * DI_];
__device__ __align__(128) float  g_y    [S_LEN * DI_];
__device__ __align__(128) __half g_yh   [S_LEN * DI_];
__device__ __align__(128) float  g_tmp  [S_LEN * D_MODEL];
__device__ __align__(128) __half g_wpad  [NL_][XDP * DI_];
__device__ __align__(128) __half g_dtwpad[NL_][DI_ * 64];
__device__ __align__(128) __half g_wbig  [NL_][2 * DI_ * D_MODEL];
__device__ __align__(128) __half g_wout  [NL_][D_MODEL * DI_];
__device__ __align__(128) __half g_wh    [VOCAB * D_MODEL];
__device__ __align__(128) float  g_P  [NCHUNK * GROUPS];
__device__ __align__(128) float  g_H  [NCHUNK * GROUPS];
__device__ __align__(128) float  g_C0 [NCHUNK * GROUPS];

// ---------------- helpers ----------------
__device__ __forceinline__ uint32_t smem_u32(const void* p) {
    uint32_t a;
    asm("{ .reg .u64 t; cvta.to.shared.u64 t, %1; cvt.u32.u64 %0, t; }" : "=r"(a) : "l"(p));
    return a;
}
__device__ __forceinline__ float silu_f(float x) { return x / (1.0f + __expf(-x)); }
__device__ __forceinline__ float sp_f(float a)   { return (a > 20.0f) ? a : log1pf(__expf(a)); }

#define CP_ASYNC16(dst, src) \
    asm volatile("cp.async.cg.shared.global [%0], [%1], 16;" :: "r"(dst), "l"(src))
#define CP_COMMIT() asm volatile("cp.async.commit_group;" ::: "memory")
#define CP_WAIT(n)  asm volatile("cp.async.wait_group %0;" :: "n"(n) : "memory")
#define LDSM4(d0, d1, d2, d3, a) \
    asm volatile("ldmatrix.sync.aligned.m8n8.x4.shared.b16 {%0,%1,%2,%3}, [%4];" \
        : "=r"(d0), "=r"(d1), "=r"(d2), "=r"(d3) : "r"(a))

__device__ __forceinline__ void mma_f16(float* c, const uint32_t* a, const uint32_t* b) {
    asm volatile(
        "mma.sync.aligned.m16n8k16.row.col.f32.f16.f16.f32 "
        "{%0,%1,%2,%3}, {%4,%5,%6,%7}, {%8,%9}, {%0,%1,%2,%3};"
        : "+f"(c[0]), "+f"(c[1]), "+f"(c[2]), "+f"(c[3])
        : "r"(a[0]), "r"(a[1]), "r"(a[2]), "r"(a[3]), "r"(b[0]), "r"(b[1]));
}

// ---------------- fp16 GEMM: 64x64 tile, 8 warps of 16x32, 4-stage ------------
// 3 CTAs/SM (24 warps/SM) — latency-hiding experiment.
#define STG_S 8192
#define NSTAGE 4
#define SMEM_GS (NSTAGE * 2 * STG_S)     // 65536

template<int OM>   // 0 fp32 out, 1 half out, 2 fp32 softplus(acc+bias) out
__global__ __launch_bounds__(256, 3)
void gemm_s(const __half* __restrict__ A, const __half* __restrict__ B,
            void* __restrict__ Cv, int K, int lda, int ldb, int ldc,
            const float* __restrict__ bias)
{
    extern __shared__ char smem[];
    const int tid = threadIdx.x, lane = tid & 31, wid = tid >> 5;
    const int wm = wid >> 1, wn = wid & 1;       // 4 m-slots x 2 n-slots
    const int bm = blockIdx.x * 64, bn = blockIdx.y * 64;
    const int nc = K >> 6;
    const int lr = lane & 7, lg = lane >> 3;

    const uint32_t sb = smem_u32(smem);
    const __half* Ab = A + (size_t)bm * lda;
    const __half* Bb = B + (size_t)bn * ldb;

    auto loadA = [&](int chunk, int st) {
        uint32_t d0 = sb + st * (2 * STG_S);
        const __half* s0 = Ab + chunk * 64;
#pragma unroll
        for (int it = 0; it < 2; it++) {
            int i = tid + it * 256;
            int r = i >> 3, q = i & 7;
            uint32_t off = ((uint32_t)r << 7) | (((uint32_t)q << 4) ^ (((uint32_t)(r & 7)) << 4));
            CP_ASYNC16(d0 + off, s0 + (size_t)r * lda + q * 8);
        }
    };
    auto loadB = [&](int chunk, int st) {
        uint32_t d0 = sb + st * (2 * STG_S) + STG_S;
        const __half* s0 = Bb + chunk * 64;
#pragma unroll
        for (int it = 0; it < 2; it++) {
            int i = tid + it * 256;
            int r = i >> 3, q = i & 7;
            uint32_t off = ((uint32_t)r << 7) | (((uint32_t)q << 4) ^ (((uint32_t)(r & 7)) << 4));
            CP_ASYNC16(d0 + off, s0 + (size_t)r * ldb + q * 8);
        }
    };

    const int a_row0 = wm * 16 + ((lg & 1) << 3) + lr;
    const int a_coff = (lg >> 1) << 4;
    const int b_row0 = wn * 32 + ((lg & 2) << 2) + lr;
    const int b_coff = (lg & 1) << 4;
    const uint32_t sw = (uint32_t)lr << 4;

    float acc[4][4];
#pragma unroll
    for (int j = 0; j < 4; j++)
#pragma unroll
        for (int v = 0; v < 4; v++) acc[j][v] = 0.0f;

    int npre = nc < 3 ? nc : 3;
    for (int c = 0; c < npre; c++) { loadA(c, c); loadB(c, c); CP_COMMIT(); }

    for (int i = 0; i < nc; i++) {
        if (i + 3 < nc) { CP_WAIT(2); } else { CP_WAIT(0); }
        __syncthreads();
        if (i + 3 < nc) {
            int s2 = (i + 3) % NSTAGE;
            loadA(i + 3, s2); loadB(i + 3, s2); CP_COMMIT();
        }
        uint32_t abase = sb + (i % NSTAGE) * (2 * STG_S);
        uint32_t bbase = abase + STG_S;
#pragma unroll
        for (int ks = 0; ks < 4; ks++) {
            const uint32_t kb = (uint32_t)ks * 32;
            uint32_t afr[4];
            {
                uint32_t ad = abase + (uint32_t)a_row0 * 128 + ((kb + a_coff) ^ sw);
                LDSM4(afr[0], afr[1], afr[2], afr[3], ad);
            }
            uint32_t bfr[4][2];
#pragma unroll
            for (int p = 0; p < 2; p++) {
                uint32_t bd = bbase + (uint32_t)(b_row0 + p * 16) * 128 + ((kb + b_coff) ^ sw);
                LDSM4(bfr[2 * p][0], bfr[2 * p][1], bfr[2 * p + 1][0], bfr[2 * p + 1][1], bd);
            }
#pragma unroll
            for (int nf = 0; nf < 4; nf++)
                mma_f16(acc[nf], afr, bfr[nf]);
        }
    }

    {
        int row = bm + wm * 16 + (lane >> 2);
#pragma unroll
        for (int nf = 0; nf < 4; nf++) {
            int col = bn + wn * 32 + nf * 8 + 2 * (lane & 3);
            if (OM == 1) {
                __half* C = (__half*)Cv;
                *(__half2*)(C + (size_t)row * ldc + col) =
                    __floats2half2_rn(acc[nf][0], acc[nf][1]);
                *(__half2*)(C + (size_t)(row + 8) * ldc + col) =
                    __floats2half2_rn(acc[nf][2], acc[nf][3]);
            } else if (OM == 2) {
                float* C = (float*)Cv;
                float b0 = bias[col], b1 = bias[col + 1];
                *(float2*)(C + (size_t)row * ldc + col) =
                    make_float2(sp_f(acc[nf][0] + b0), sp_f(acc[nf][1] + b1));
                *(float2*)(C + (size_t)(row + 8) * ldc + col) =
                    make_float2(sp_f(acc[nf][2] + b0), sp_f(acc[nf][3] + b1));
            } else {
                float* C = (float*)Cv;
                *(float2*)(C + (size_t)row * ldc + col) =
                    make_float2(acc[nf][0], acc[nf][1]);
                *(float2*)(C + (size_t)(row + 8) * ldc + col) =
                    make_float2(acc[nf][2], acc[nf][3]);
            }
        }
    }
}

// ---------------- elementwise / small kernels ----------------
__global__ void roundcopy_h(__half2* __restrict__ dst, const float4* __restrict__ src, int n4) {
    int i = blockIdx.x * blockDim.x + threadIdx.x;
    if (i < n4) {
        float4 v = src[i];
        dst[2 * i]     = __floats2half2_rn(v.x, v.y);
        dst[2 * i + 1] = __floats2half2_rn(v.z, v.w);
    }
}

__global__ void embed_kernel(const int* __restrict__ tokens,
                             const float* __restrict__ emb) {
    int i = blockIdx.x * blockDim.x + threadIdx.x;
    if (i < S_LEN * D_MODEL) {
        int l = i / D_MODEL, d = i - l * D_MODEL;
        float e = emb[(size_t)tokens[l] * D_MODEL + d];
        g_x[i]  = e;
        g_xh[i] = __float2half_rn(e);
    }
}

__global__ void padw_kernel(const float* __restrict__ xw, int L) {
    int i = blockIdx.x * 256 + threadIdx.x;
    if (i >= XDP * DI_) return;
    int row = i / DI_, col = i - row * DI_;
    g_wpad[L][i] = (row < 80) ? __float2half_rn(xw[((size_t)L * 80 + row) * DI_ + col])
                              : __half(0.0f);
}

__global__ void paddt_kernel(const float* __restrict__ dw, int L) {
    int i = blockIdx.x * 256 + threadIdx.x;
    if (i >= DI_ * 64) return;
    int row = i >> 6, col = i & 63;
    g_dtwpad[L][i] = (col < DTRANK) ? __float2half_rn(dw[((size_t)L * DI_ + row) * DTRANK + col])
                                    : __half(0.0f);
}

__global__ void conv_silu_kernel(const float* __restrict__ conv_w,
                                 const float* __restrict__ conv_b, int layer) {
    int i = blockIdx.x * blockDim.x + threadIdx.x;
    if (i >= S_LEN * DI_) return;
    int t = i / DI_, c = i - t * DI_;
    const float* w = conv_w + ((size_t)layer * DI_ + c) * K_CONV;
    float acc = conv_b[layer * DI_ + c];
#pragma unroll
    for (int k = 0; k < K_CONV; k++) {
        int tt = t - (K_CONV - 1) + k;
        if (tt >= 0) acc += w[k] * g_xz[(size_t)tt * 2 * DI_ + c];
    }
    g_xsh[i] = __float2half_rn(silu_f(acc));
}

// ---------------- chunked scan, per-channel layout (R10 form) -----------------
__global__ __launch_bounds__(128)
void scan_p1(const float* __restrict__ A_log, int layer) {
    int c = blockIdx.x * 128 + threadIdx.x;
    int j = blockIdx.y;
    float Acn[N_ST];
#pragma unroll
    for (int n = 0; n < N_ST; n++)
        Acn[n] = -expf(A_log[((size_t)layer * DI_ + c) * N_ST + n]);
    float h[N_ST];
#pragma unroll
    for (int n = 0; n < N_ST; n++) h[n] = 0.0f;
    float Sdt = 0.0f;
    int t0 = j * CLEN;
    for (int t = t0; t < t0 + CLEN; t++) {
        float dtv = g_dtl[(size_t)t * DI_ + c];
        float xv  = __half2float(g_xsh[(size_t)t * DI_ + c]);
        float dx  = dtv * xv;
        Sdt += dtv;
        const __half2* bc = (const __half2*)(g_xdblh + (size_t)t * XDP + DTRANK);
        float y = 0.0f;
#pragma unroll
        for (int q = 0; q < 8; q++) {
            float2 B2 = __half22float2(bc[q]);
            float2 C2 = __half22float2(bc[8 + q]);
            float dA0 = __expf(dtv * Acn[2 * q]);
            float dA1 = __expf(dtv * Acn[2 * q + 1]);
            h[2 * q]     = dA0 * h[2 * q]     + dx * B2.x;
            h[2 * q + 1] = dA1 * h[2 * q + 1] + dx * B2.y;
            y += h[2 * q] * C2.x + h[2 * q + 1] * C2.y;
        }
        g_y[(size_t)t * DI_ + c] = y;
    }
    float* Hp = g_H + (size_t)j * GROUPS + (size_t)c * N_ST;
    float* Pp = g_P + (size_t)j * GROUPS + (size_t)c * N_ST;
#pragma unroll
    for (int n = 0; n < N_ST; n++) {
        Hp[n] = h[n];
        Pp[n] = __expf(Sdt * Acn[n]);
    }
}

__global__ void scan_p2() {
    int idx = blockIdx.x * blockDim.x + threadIdx.x;
    if (idx >= GROUPS) return;
    float carry = 0.0f;
#pragma unroll
    for (int j = 0; j < NCHUNK; j++) {
        g_C0[j * GROUPS + idx] = carry;
        carry = g_H[j * GROUPS + idx] + g_P[j * GROUPS + idx] * carry;
    }
}

__global__ __launch_bounds__(128)
void scan_p3(const float* __restrict__ A_log, const float* __restrict__ Dp, int layer) {
    int c = blockIdx.x * 128 + threadIdx.x;
    int j = blockIdx.y;
    float Dpc = Dp[layer * DI_ + c];
    int t0 = j * CLEN;
    if (j == 0) {
        for (int t = t0; t < t0 + CLEN; t++) {
            float xv = __half2float(g_xsh[(size_t)t * DI_ + c]);
            float z  = g_xz[(size_t)t * 2 * DI_ + DI_ + c];
            g_yh[(size_t)t * DI_ + c] = __float2half_rn(
                (g_y[(size_t)t * DI_ + c] + xv * Dpc) * silu_f(z));
        }
        return;
    }
    float Acn[N_ST], w[N_ST];
    const float* Cp = g_C0 + (size_t)j * GROUPS + (size_t)c * N_ST;
#pragma unroll
    for (int n = 0; n < N_ST; n++) {
        Acn[n] = -expf(A_log[((size_t)layer * DI_ + c) * N_ST + n]);
        w[n]   = Cp[n];
    }
    float S = 0.0f;
    for (int t = t0; t < t0 + CLEN; t++) {
        float dtv = g_dtl[(size_t)t * DI_ + c];
        S += dtv;
        const __half2* cc = (const __half2*)(g_xdblh + (size_t)t * XDP + DTRANK + N_ST);
        float v = 0.0f;
#pragma unroll
        for (int q = 0; q < 8; q++) {
            float2 C2 = __half22float2(cc[q]);
            v += C2.x * __expf(S * Acn[2 * q])     * w[2 * q];
            v += C2.y * __expf(S * Acn[2 * q + 1]) * w[2 * q + 1];
        }
        float xv = __half2float(g_xsh[(size_t)t * DI_ + c]);
        float z  = g_xz[(size_t)t * 2 * DI_ + DI_ + c];
        g_yh[(size_t)t * DI_ + c] = __float2half_rn(
            (g_y[(size_t)t * DI_ + c] + v + xv * Dpc) * silu_f(z));
    }
}

__global__ __launch_bounds__(256)
void ln_kernel(const float* __restrict__ gam, const float* __restrict__ bet, int layer) {
    int l = blockIdx.x;
    __shared__ float rsum[8], rsq[8];
    float sum = 0.0f, sq = 0.0f;
    for (int d = threadIdx.x; d < D_MODEL; d += 256) {
        float v = g_x[(size_t)l * D_MODEL + d] + g_tmp[(size_t)l * D_MODEL + d];
        sum += v; sq += v * v;
    }
#pragma unroll
    for (int o = 16; o > 0; o >>= 1) {
        sum += __shfl_down_sync(0xffffffffu, sum, o);
        sq  += __shfl_down_sync(0xffffffffu, sq, o);
    }
    int wid = threadIdx.x >> 5;
    if ((threadIdx.x & 31) == 0) { rsum[wid] = sum; rsq[wid] = sq; }
    __syncthreads();
    if (threadIdx.x == 0) {
        float s = 0.0f, q = 0.0f;
#pragma unroll
        for (int w = 0; w < 8; w++) { s += rsum[w]; q += rsq[w]; }
        rsum[0] = s; rsq[0] = q;
    }
    __syncthreads();
    float mu  = rsum[0] / (float)D_MODEL;
    float var = rsq[0] / (float)D_MODEL - mu * mu;
    float rinv = rsqrtf(var + 1e-5f);
    for (int d = threadIdx.x; d < D_MODEL; d += 256) {
        float v = g_x[(size_t)l * D_MODEL + d] + g_tmp[(size_t)l * D_MODEL + d];
        float o = (v - mu) * rinv * gam[layer * D_MODEL + d] + bet[layer * D_MODEL + d];
        g_x [(size_t)l * D_MODEL + d] = o;
        g_xh[(size_t)l * D_MODEL + d] = __float2half_rn(o);
    }
}

// ---------------- launch ----------------
extern "C" void kernel_launch(void* const* d_in, const int* in_sizes, int n_in,
                              void* d_out, int out_size) {
    const int*   tokens  = (const int*)  d_in[0];
    const float* emb     = (const float*)d_in[1];
    const float* in_w    = (const float*)d_in[2];
    const float* conv_w  = (const float*)d_in[3];
    const float* conv_b  = (const float*)d_in[4];
    const float* xproj_w = (const float*)d_in[5];
    const float* dt_w    = (const float*)d_in[6];
    const float* dt_b    = (const float*)d_in[7];
    const float* A_log   = (const float*)d_in[8];
    const float* Dp      = (const float*)d_in[9];
    const float* out_w   = (const float*)d_in[10];
    const float* ln_g    = (const float*)d_in[11];
    const float* ln_b    = (const float*)d_in[12];
    const float* head_w  = (const float*)d_in[13];
    float* out = (float*)d_out;

    static float *px = nullptr, *pxz, *pdtl, *py, *ptmp;
    static __half *pxh, *pxsh, *pxdblh, *pyh, *pwh;
    static __half *pwpad[NL_], *pdtw[NL_], *pwbig[NL_], *pwout[NL_];
    static cudaStream_t s1;
    static cudaEvent_t evFork, evWh, evJoin;
    static cudaEvent_t evIn[NL_], evPP[NL_], evOw[NL_];
    if (!px) {
        cudaGetSymbolAddress((void**)&pxz,    g_xz);
        cudaGetSymbolAddress((void**)&pdtl,   g_dtl);
        cudaGetSymbolAddress((void**)&py,     g_y);
        cudaGetSymbolAddress((void**)&ptmp,   g_tmp);
        cudaGetSymbolAddress((void**)&pxh,    g_xh);
        cudaGetSymbolAddress((void**)&pxsh,   g_xsh);
        cudaGetSymbolAddress((void**)&pxdblh, g_xdblh);
        cudaGetSymbolAddress((void**)&pyh,    g_yh);
        cudaGetSymbolAddress((void**)&pwh,    g_wh);
        __half* hb;
        cudaGetSymbolAddress((void**)&hb, g_wpad);
        for (int L = 0; L < NL_; L++) pwpad[L] = hb + (size_t)L * XDP * DI_;
        cudaGetSymbolAddress((void**)&hb, g_dtwpad);
        for (int L = 0; L < NL_; L++) pdtw[L] = hb + (size_t)L * DI_ * 64;
        cudaGetSymbolAddress((void**)&hb, g_wbig);
        for (int L = 0; L < NL_; L++) pwbig[L] = hb + (size_t)L * 2 * DI_ * D_MODEL;
        cudaGetSymbolAddress((void**)&hb, g_wout);
        for (int L = 0; L < NL_; L++) pwout[L] = hb + (size_t)L * D_MODEL * DI_;
        cudaFuncSetAttribute(gemm_s<0>,
                             cudaFuncAttributeMaxDynamicSharedMemorySize, SMEM_GS);
        cudaFuncSetAttribute(gemm_s<1>,
                             cudaFuncAttributeMaxDynamicSharedMemorySize, SMEM_GS);
        cudaFuncSetAttribute(gemm_s<2>,
                             cudaFuncAttributeMaxDynamicSharedMemorySize, SMEM_GS);
        cudaStreamCreateWithFlags(&s1, cudaStreamNonBlocking);
        cudaEventCreateWithFlags(&evFork, cudaEventDisableTiming);
        cudaEventCreateWithFlags(&evWh,   cudaEventDisableTiming);
        cudaEventCreateWithFlags(&evJoin, cudaEventDisableTiming);
        for (int L = 0; L < NL_; L++) {
            cudaEventCreateWithFlags(&evIn[L], cudaEventDisableTiming);
            cudaEventCreateWithFlags(&evPP[L], cudaEventDisableTiming);
            cudaEventCreateWithFlags(&evOw[L], cudaEventDisableTiming);
        }
        cudaGetSymbolAddress((void**)&px, g_x);
    }

    cudaEventRecord(evFork, 0);
    cudaStreamWaitEvent(s1, evFork, 0);

    embed_kernel<<<(S_LEN * D_MODEL + 255) / 256, 256>>>(tokens, emb);          // idx 0

    roundcopy_h<<<(2 * DI_ * D_MODEL / 4 + 255) / 256, 256, 0, s1>>>(           // idx 1
        (__half2*)pwbig[0], (const float4*)in_w, 2 * DI_ * D_MODEL / 4);
    cudaEventRecord(evIn[0], s1);
    padw_kernel<<<(XDP * DI_ + 255) / 256, 256, 0, s1>>>(xproj_w, 0);           // idx 2

    // in-proj L0 (profiled launch idx 3)
    cudaStreamWaitEvent(0, evIn[0], 0);
    gemm_s<0><<<dim3(S_LEN / 64, 2 * DI_ / 64), 256, SMEM_GS>>>(
        pxh, pwbig[0], pxz, D_MODEL, D_MODEL, D_MODEL, 2 * DI_, nullptr);       // idx 3

    paddt_kernel<<<(DI_ * 64 + 255) / 256, 256, 0, s1>>>(dt_w, 0);
    cudaEventRecord(evPP[0], s1);
    roundcopy_h<<<(D_MODEL * DI_ / 4 + 255) / 256, 256, 0, s1>>>(
        (__half2*)pwout[0], (const float4*)out_w, D_MODEL * DI_ / 4);
    cudaEventRecord(evOw[0], s1);
    roundcopy_h<<<(2 * DI_ * D_MODEL / 4 + 255) / 256, 256, 0, s1>>>(
        (__half2*)pwbig[1], (const float4*)(in_w + (size_t)2 * DI_ * D_MODEL),
        2 * DI_ * D_MODEL / 4);
    cudaEventRecord(evIn[1], s1);
    padw_kernel<<<(XDP * DI_ + 255) / 256, 256, 0, s1>>>(xproj_w, 1);
    paddt_kernel<<<(DI_ * 64 + 255) / 256, 256, 0, s1>>>(dt_w, 1);
    cudaEventRecord(evPP[1], s1);
    roundcopy_h<<<(D_MODEL * DI_ / 4 + 255) / 256, 256, 0, s1>>>(
        (__half2*)pwout[1], (const float4*)(out_w + (size_t)D_MODEL * DI_),
        D_MODEL * DI_ / 4);
    cudaEventRecord(evOw[1], s1);
    roundcopy_h<<<(VOCAB * D_MODEL / 4 + 255) / 256, 256, 0, s1>>>(
        (__half2*)pwh, (const float4*)head_w, VOCAB * D_MODEL / 4);
    cudaEventRecord(evWh, s1);
    cudaEventRecord(evJoin, s1);

    for (int L = 0; L < NL_; L++) {
        if (L > 0) {
            cudaStreamWaitEvent(0, evIn[L], 0);
            gemm_s<0><<<dim3(S_LEN / 64, 2 * DI_ / 64), 256, SMEM_GS>>>(
                pxh, pwbig[L], pxz, D_MODEL, D_MODEL, D_MODEL, 2 * DI_, nullptr);
        }
        conv_silu_kernel<<<(S_LEN * DI_ + 255) / 256, 256>>>(conv_w, conv_b, L);

        cudaStreamWaitEvent(0, evPP[L], 0);
        gemm_s<1><<<dim3(S_LEN / 64, XDP / 64), 256, SMEM_GS>>>(
            pxsh, pwpad[L], pxdblh, DI_, DI_, DI_, XDP, nullptr);
        gemm_s<2><<<dim3(S_LEN / 64, DI_ / 64), 256, SMEM_GS>>>(
            pxdblh, pdtw[L], pdtl, 64, XDP, 64, DI_, dt_b + (size_t)L * DI_);

        scan_p1<<<dim3(DI_ / 128, NCHUNK), 128>>>(A_log, L);
        scan_p2<<<(GROUPS + 255) / 256, 256>>>();
        scan_p3<<<dim3(DI_ / 128, NCHUNK), 128>>>(A_log, Dp, L);

        cudaStreamWaitEvent(0, evOw[L], 0);
        gemm_s<0><<<dim3(S_LEN / 64, D_MODEL / 64), 256, SMEM_GS>>>(
            pyh, pwout[L], ptmp, DI_, DI_, DI_, D_MODEL, nullptr);

        ln_kernel<<<S_LEN, 256>>>(ln_g, ln_b, L);
    }

    cudaStreamWaitEvent(0, evWh, 0);
    cudaStreamWaitEvent(0, evJoin, 0);
    gemm_s<0><<<dim3(S_LEN / 64, VOCAB / 64), 256, SMEM_GS>>>(
        pxh, pwh, out, D_MODEL, D_MODEL, D_MODEL, VOCAB, nullptr);
}

// round 13
// speedup vs baseline: 1.1045x; 1.1045x over previous
#include <cuda_runtime.h>
#include <cuda_fp16.h>
#include <cstdint>
#include <math.h>

#define S_LEN   1024
#define D_MODEL 768
#define DI_     1536
#define N_ST    16
#define K_CONV  4
#define DTRANK  48
#define XDP     128
#define VOCAB   32000
#define NL_     2
#define NCHUNK  32
#define CLEN    32
#define GROUPS  (DI_ * N_ST)

// ---------------- scratch ----------------
__device__ __align__(128) float  g_x    [S_LEN * D_MODEL];
__device__ __align__(128) __half g_xh   [S_LEN * D_MODEL];
__device__ __align__(128) float  g_xz   [S_LEN * 2 * DI_];
__device__ __align__(128) __half g_xsh  [S_LEN * DI_];
__device__ __align__(128) __half g_xdblh[S_LEN * XDP];
__device__ __align__(128) float  g_dtl  [S_LEN * DI_];
__device__ __align__(128) __half g_yh   [S_LEN * DI_];
__device__ __align__(128) float  g_tmp  [S_LEN * D_MODEL];
__device__ __align__(128) __half g_wpad  [NL_][XDP * DI_];
__device__ __align__(128) __half g_dtwpad[NL_][DI_ * 64];
__device__ __align__(128) __half g_wbig  [NL_][2 * DI_ * D_MODEL];
__device__ __align__(128) __half g_wout  [NL_][D_MODEL * DI_];
__device__ __align__(128) __half g_wh    [VOCAB * D_MODEL];
__device__ __align__(128) float  g_P  [NCHUNK * GROUPS];
__device__ __align__(128) float  g_H  [NCHUNK * GROUPS];
__device__ __align__(128) float  g_I  [NCHUNK * GROUPS];
__device__ int g_flag [NCHUNK * DI_];
__device__ int g_epoch;

// ---------------- helpers ----------------
__device__ __forceinline__ uint32_t smem_u32(const void* p) {
    uint32_t a;
    asm("{ .reg .u64 t; cvta.to.shared.u64 t, %1; cvt.u32.u64 %0, t; }" : "=r"(a) : "l"(p));
    return a;
}
__device__ __forceinline__ float silu_f(float x) { return x / (1.0f + __expf(-x)); }
__device__ __forceinline__ float sp_f(float a)   { return (a > 20.0f) ? a : log1pf(__expf(a)); }

#define CP_ASYNC16(dst, src) \
    asm volatile("cp.async.cg.shared.global [%0], [%1], 16;" :: "r"(dst), "l"(src))
#define CP_COMMIT() asm volatile("cp.async.commit_group;" ::: "memory")
#define CP_WAIT(n)  asm volatile("cp.async.wait_group %0;" :: "n"(n) : "memory")
#define LDSM4(d0, d1, d2, d3, a) \
    asm volatile("ldmatrix.sync.aligned.m8n8.x4.shared.b16 {%0,%1,%2,%3}, [%4];" \
        : "=r"(d0), "=r"(d1), "=r"(d2), "=r"(d3) : "r"(a))

__device__ __forceinline__ void mma_f16(float* c, const uint32_t* a, const uint32_t* b) {
    asm volatile(
        "mma.sync.aligned.m16n8k16.row.col.f32.f16.f16.f32 "
        "{%0,%1,%2,%3}, {%4,%5,%6,%7}, {%8,%9}, {%0,%1,%2,%3};"
        : "+f"(c[0]), "+f"(c[1]), "+f"(c[2]), "+f"(c[3])
        : "r"(a[0]), "r"(a[1]), "r"(a[2]), "r"(a[3]), "r"(b[0]), "r"(b[1]));
}

// ---------------- fp16 GEMM: 64x64, 4 warps, 3-stage, 4 CTAs/SM (R9 config) ---
#define STG_S 8192
#define SMEM_GS (3 * 2 * STG_S)

template<int OM>   // 0 fp32 out, 1 half out, 2 fp32 softplus(acc+bias) out
__global__ __launch_bounds__(128, 4)
void gemm_s(const __half* __restrict__ A, const __half* __restrict__ B,
            void* __restrict__ Cv, int K, int lda, int ldb, int ldc,
            const float* __restrict__ bias)
{
    extern __shared__ char smem[];
    const int tid = threadIdx.x, lane = tid & 31, wid = tid >> 5;
    const int wm = wid >> 1, wn = wid & 1;
    const int bm = blockIdx.x * 64, bn = blockIdx.y * 64;
    const int nc = K >> 6;
    const int lr = lane & 7, lg = lane >> 3;

    const uint32_t sb = smem_u32(smem);
    const __half* Ab = A + (size_t)bm * lda;
    const __half* Bb = B + (size_t)bn * ldb;

    auto loadA = [&](int chunk, int st) {
        uint32_t d0 = sb + st * (2 * STG_S);
        const __half* s0 = Ab + chunk * 64;
#pragma unroll
        for (int it = 0; it < 4; it++) {
            int i = tid + it * 128;
            int r = i >> 3, q = i & 7;
            uint32_t off = ((uint32_t)r << 7) | (((uint32_t)q << 4) ^ (((uint32_t)(r & 7)) << 4));
            CP_ASYNC16(d0 + off, s0 + (size_t)r * lda + q * 8);
        }
    };
    auto loadB = [&](int chunk, int st) {
        uint32_t d0 = sb + st * (2 * STG_S) + STG_S;
        const __half* s0 = Bb + chunk * 64;
#pragma unroll
        for (int it = 0; it < 4; it++) {
            int i = tid + it * 128;
            int r = i >> 3, q = i & 7;
            uint32_t off = ((uint32_t)r << 7) | (((uint32_t)q << 4) ^ (((uint32_t)(r & 7)) << 4));
            CP_ASYNC16(d0 + off, s0 + (size_t)r * ldb + q * 8);
        }
    };

    const int a_row0 = wm * 32 + ((lg & 1) << 3) + lr;
    const int a_coff = (lg >> 1) << 4;
    const int b_row0 = wn * 32 + ((lg & 2) << 2) + lr;
    const int b_coff = (lg & 1) << 4;
    const uint32_t sw = (uint32_t)lr << 4;

    float acc[2][4][4];
#pragma unroll
    for (int i = 0; i < 2; i++)
#pragma unroll
        for (int j = 0; j < 4; j++)
#pragma unroll
            for (int v = 0; v < 4; v++) acc[i][j][v] = 0.0f;

    int npre = nc < 2 ? nc : 2;
    for (int c = 0; c < npre; c++) { loadA(c, c); loadB(c, c); CP_COMMIT(); }

    for (int i = 0; i < nc; i++) {
        if (i + 2 < nc) { CP_WAIT(1); } else { CP_WAIT(0); }
        __syncthreads();
        if (i + 2 < nc) {
            int s2 = (i + 2) % 3;
            loadA(i + 2, s2); loadB(i + 2, s2); CP_COMMIT();
        }
        uint32_t abase = sb + (i % 3) * (2 * STG_S);
        uint32_t bbase = abase + STG_S;
#pragma unroll
        for (int ks = 0; ks < 4; ks++) {
            const uint32_t kb = (uint32_t)ks * 32;
            uint32_t afr[2][4];
#pragma unroll
            for (int mf = 0; mf < 2; mf++) {
                uint32_t ad = abase + (uint32_t)(a_row0 + mf * 16) * 128 + ((kb + a_coff) ^ sw);
                LDSM4(afr[mf][0], afr[mf][1], afr[mf][2], afr[mf][3], ad);
            }
            uint32_t bfr[4][2];
#pragma unroll
            for (int p = 0; p < 2; p++) {
                uint32_t bd = bbase + (uint32_t)(b_row0 + p * 16) * 128 + ((kb + b_coff) ^ sw);
                LDSM4(bfr[2 * p][0], bfr[2 * p][1], bfr[2 * p + 1][0], bfr[2 * p + 1][1], bd);
            }
#pragma unroll
            for (int mf = 0; mf < 2; mf++)
#pragma unroll
                for (int nf = 0; nf < 4; nf++)
                    mma_f16(acc[mf][nf], afr[mf], bfr[nf]);
        }
    }

#pragma unroll
    for (int mf = 0; mf < 2; mf++) {
        int row = bm + wm * 32 + mf * 16 + (lane >> 2);
#pragma unroll
        for (int nf = 0; nf < 4; nf++) {
            int col = bn + wn * 32 + nf * 8 + 2 * (lane & 3);
            if (OM == 1) {
                __half* C = (__half*)Cv;
                *(__half2*)(C + (size_t)row * ldc + col) =
                    __floats2half2_rn(acc[mf][nf][0], acc[mf][nf][1]);
                *(__half2*)(C + (size_t)(row + 8) * ldc + col) =
                    __floats2half2_rn(acc[mf][nf][2], acc[mf][nf][3]);
            } else if (OM == 2) {
                float* C = (float*)Cv;
                float b0 = bias[col], b1 = bias[col + 1];
                *(float2*)(C + (size_t)row * ldc + col) =
                    make_float2(sp_f(acc[mf][nf][0] + b0), sp_f(acc[mf][nf][1] + b1));
                *(float2*)(C + (size_t)(row + 8) * ldc + col) =
                    make_float2(sp_f(acc[mf][nf][2] + b0), sp_f(acc[mf][nf][3] + b1));
            } else {
                float* C = (float*)Cv;
                *(float2*)(C + (size_t)row * ldc + col) =
                    make_float2(acc[mf][nf][0], acc[mf][nf][1]);
                *(float2*)(C + (size_t)(row + 8) * ldc + col) =
                    make_float2(acc[mf][nf][2], acc[mf][nf][3]);
            }
        }
    }
}

// ---------------- elementwise / small kernels ----------------
__global__ void roundcopy_h(__half2* __restrict__ dst, const float4* __restrict__ src, int n4) {
    int i = blockIdx.x * blockDim.x + threadIdx.x;
    if (i < n4) {
        float4 v = src[i];
        dst[2 * i]     = __floats2half2_rn(v.x, v.y);
        dst[2 * i + 1] = __floats2half2_rn(v.z, v.w);
    }
}

__global__ void embed_kernel(const int* __restrict__ tokens,
                             const float* __restrict__ emb) {
    int i = blockIdx.x * blockDim.x + threadIdx.x;
    if (i < S_LEN * D_MODEL) {
        int l = i / D_MODEL, d = i - l * D_MODEL;
        float e = emb[(size_t)tokens[l] * D_MODEL + d];
        g_x[i]  = e;
        g_xh[i] = __float2half_rn(e);
    }
}

__global__ void padw_kernel(const float* __restrict__ xw, int L) {
    int i = blockIdx.x * 256 + threadIdx.x;
    if (i >= XDP * DI_) return;
    int row = i / DI_, col = i - row * DI_;
    g_wpad[L][i] = (row < 80) ? __float2half_rn(xw[((size_t)L * 80 + row) * DI_ + col])
                              : __half(0.0f);
}

__global__ void paddt_kernel(const float* __restrict__ dw, int L) {
    int i = blockIdx.x * 256 + threadIdx.x;
    if (i >= DI_ * 64) return;
    int row = i >> 6, col = i & 63;
    g_dtwpad[L][i] = (col < DTRANK) ? __float2half_rn(dw[((size_t)L * DI_ + row) * DTRANK + col])
                                    : __half(0.0f);
}

__global__ void conv_silu_kernel(const float* __restrict__ conv_w,
                                 const float* __restrict__ conv_b, int layer) {
    int i = blockIdx.x * blockDim.x + threadIdx.x;
    if (i >= S_LEN * DI_) return;
    int t = i / DI_, c = i - t * DI_;
    const float* w = conv_w + ((size_t)layer * DI_ + c) * K_CONV;
    float acc = conv_b[layer * DI_ + c];
#pragma unroll
    for (int k = 0; k < K_CONV; k++) {
        int tt = t - (K_CONV - 1) + k;
        if (tt >= 0) acc += w[k] * g_xz[(size_t)tt * 2 * DI_ + c];
    }
    g_xsh[i] = __float2half_rn(silu_f(acc));
}

__global__ void bump_epoch() { if (threadIdx.x == 0) atomicAdd(&g_epoch, 1); }

// ---------------- single-pass scan with decoupled look-back -------------------
// thread = (channel, chunk). Local scan (y in regs) -> publish aggregate (P,H)
// -> look-back for carry -> publish inclusive -> correction + gate. Waits only
// target lower chunk indices => acyclic => no deadlock. Epoch makes flags
// replay-safe (stale epochs compare as not-ready).
__global__ __launch_bounds__(128)
void scan_fused(const float* __restrict__ A_log, const float* __restrict__ Dp,
                int layer) {
    const int c = blockIdx.x * 128 + threadIdx.x;
    const int j = blockIdx.y;
    const int e2 = 2 * (*(volatile int*)&g_epoch);
    const int t0 = j * CLEN;

    float Acn[N_ST];
#pragma unroll
    for (int n = 0; n < N_ST; n++)
        Acn[n] = -expf(A_log[((size_t)layer * DI_ + c) * N_ST + n]);

    float h[N_ST];
#pragma unroll
    for (int n = 0; n < N_ST; n++) h[n] = 0.0f;
    float yloc[CLEN];
    float Sdt = 0.0f;
#pragma unroll 4
    for (int tt = 0; tt < CLEN; tt++) {
        int t = t0 + tt;
        float dtv = g_dtl[(size_t)t * DI_ + c];
        float xv  = __half2float(g_xsh[(size_t)t * DI_ + c]);
        float dx  = dtv * xv;
        Sdt += dtv;
        const __half2* bc = (const __half2*)(g_xdblh + (size_t)t * XDP + DTRANK);
        float y = 0.0f;
#pragma unroll
        for (int q = 0; q < 8; q++) {
            float2 B2 = __half22float2(bc[q]);
            float2 C2 = __half22float2(bc[8 + q]);
            float dA0 = __expf(dtv * Acn[2 * q]);
            float dA1 = __expf(dtv * Acn[2 * q + 1]);
            h[2 * q]     = dA0 * h[2 * q]     + dx * B2.x;
            h[2 * q + 1] = dA1 * h[2 * q + 1] + dx * B2.y;
            y += h[2 * q] * C2.x + h[2 * q + 1] * C2.y;
        }
        yloc[tt] = y;
    }

    float Pself[N_ST];
#pragma unroll
    for (int n = 0; n < N_ST; n++) Pself[n] = __expf(Sdt * Acn[n]);

    // publish aggregate
    {
        float* Hp = g_H + (size_t)j * GROUPS + (size_t)c * N_ST;
        float* Pp = g_P + (size_t)j * GROUPS + (size_t)c * N_ST;
#pragma unroll
        for (int n = 0; n < N_ST; n++) { __stcg(&Hp[n], h[n]); __stcg(&Pp[n], Pself[n]); }
        __threadfence();
        ((volatile int*)g_flag)[j * DI_ + c] = e2 + 1;
    }

    // look-back
    float carry[N_ST];
#pragma unroll
    for (int n = 0; n < N_ST; n++) carry[n] = 0.0f;
    if (j > 0) {
        float prod[N_ST];
#pragma unroll
        for (int n = 0; n < N_ST; n++) prod[n] = 1.0f;
        int jj = j - 1;
        while (true) {
            int f = ((volatile int*)g_flag)[jj * DI_ + c];
            while (f < e2 + 1) {
                __nanosleep(60);
                f = ((volatile int*)g_flag)[jj * DI_ + c];
            }
            __threadfence();
            if (f >= e2 + 2) {
                const float* Iq = g_I + (size_t)jj * GROUPS + (size_t)c * N_ST;
#pragma unroll
                for (int n = 0; n < N_ST; n++) carry[n] += prod[n] * __ldcg(&Iq[n]);
                break;
            }
            const float* Hq = g_H + (size_t)jj * GROUPS + (size_t)c * N_ST;
            const float* Pq = g_P + (size_t)jj * GROUPS + (size_t)c * N_ST;
#pragma unroll
            for (int n = 0; n < N_ST; n++) {
                carry[n] += prod[n] * __ldcg(&Hq[n]);
                prod[n]  *= __ldcg(&Pq[n]);
            }
            if (--jj < 0) break;
        }
    }

    // publish inclusive
    {
        float* Iq = g_I + (size_t)j * GROUPS + (size_t)c * N_ST;
#pragma unroll
        for (int n = 0; n < N_ST; n++) __stcg(&Iq[n], h[n] + Pself[n] * carry[n]);
        __threadfence();
        ((volatile int*)g_flag)[j * DI_ + c] = e2 + 2;
    }

    // correction + gate
    float Dpc = Dp[layer * DI_ + c];
    if (j == 0) {
#pragma unroll 4
        for (int tt = 0; tt < CLEN; tt++) {
            int t = t0 + tt;
            float xv = __half2float(g_xsh[(size_t)t * DI_ + c]);
            float z  = g_xz[(size_t)t * 2 * DI_ + DI_ + c];
            g_yh[(size_t)t * DI_ + c] = __float2half_rn(
                (yloc[tt] + xv * Dpc) * silu_f(z));
        }
    } else {
        float S = 0.0f;
#pragma unroll 4
        for (int tt = 0; tt < CLEN; tt++) {
            int t = t0 + tt;
            float dtv = g_dtl[(size_t)t * DI_ + c];
            S += dtv;
            const __half2* cc = (const __half2*)(g_xdblh + (size_t)t * XDP + DTRANK + N_ST);
            float v = 0.0f;
#pragma unroll
            for (int q = 0; q < 8; q++) {
                float2 C2 = __half22float2(cc[q]);
                v += C2.x * __expf(S * Acn[2 * q])     * carry[2 * q];
                v += C2.y * __expf(S * Acn[2 * q + 1]) * carry[2 * q + 1];
            }
            float xv = __half2float(g_xsh[(size_t)t * DI_ + c]);
            float z  = g_xz[(size_t)t * 2 * DI_ + DI_ + c];
            g_yh[(size_t)t * DI_ + c] = __float2half_rn(
                (yloc[tt] + v + xv * Dpc) * silu_f(z));
        }
    }
}

__global__ __launch_bounds__(256)
void ln_kernel(const float* __restrict__ gam, const float* __restrict__ bet, int layer) {
    int l = blockIdx.x;
    __shared__ float rsum[8], rsq[8];
    float sum = 0.0f, sq = 0.0f;
    for (int d = threadIdx.x; d < D_MODEL; d += 256) {
        float v = g_x[(size_t)l * D_MODEL + d] + g_tmp[(size_t)l * D_MODEL + d];
        sum += v; sq += v * v;
    }
#pragma unroll
    for (int o = 16; o > 0; o >>= 1) {
        sum += __shfl_down_sync(0xffffffffu, sum, o);
        sq  += __shfl_down_sync(0xffffffffu, sq, o);
    }
    int wid = threadIdx.x >> 5;
    if ((threadIdx.x & 31) == 0) { rsum[wid] = sum; rsq[wid] = sq; }
    __syncthreads();
    if (threadIdx.x == 0) {
        float s = 0.0f, q = 0.0f;
#pragma unroll
        for (int w = 0; w < 8; w++) { s += rsum[w]; q += rsq[w]; }
        rsum[0] = s; rsq[0] = q;
    }
    __syncthreads();
    float mu  = rsum[0] / (float)D_MODEL;
    float var = rsq[0] / (float)D_MODEL - mu * mu;
    float rinv = rsqrtf(var + 1e-5f);
    for (int d = threadIdx.x; d < D_MODEL; d += 256) {
        float v = g_x[(size_t)l * D_MODEL + d] + g_tmp[(size_t)l * D_MODEL + d];
        float o = (v - mu) * rinv * gam[layer * D_MODEL + d] + bet[layer * D_MODEL + d];
        g_x [(size_t)l * D_MODEL + d] = o;
        g_xh[(size_t)l * D_MODEL + d] = __float2half_rn(o);
    }
}

// ---------------- launch ----------------
extern "C" void kernel_launch(void* const* d_in, const int* in_sizes, int n_in,
                              void* d_out, int out_size) {
    const int*   tokens  = (const int*)  d_in[0];
    const float* emb     = (const float*)d_in[1];
    const float* in_w    = (const float*)d_in[2];
    const float* conv_w  = (const float*)d_in[3];
    const float* conv_b  = (const float*)d_in[4];
    const float* xproj_w = (const float*)d_in[5];
    const float* dt_w    = (const float*)d_in[6];
    const float* dt_b    = (const float*)d_in[7];
    const float* A_log   = (const float*)d_in[8];
    const float* Dp      = (const float*)d_in[9];
    const float* out_w   = (const float*)d_in[10];
    const float* ln_g    = (const float*)d_in[11];
    const float* ln_b    = (const float*)d_in[12];
    const float* head_w  = (const float*)d_in[13];
    float* out = (float*)d_out;

    static float *px = nullptr, *pxz, *pdtl, *ptmp;
    static __half *pxh, *pxsh, *pxdblh, *pyh, *pwh;
    static __half *pwpad[NL_], *pdtw[NL_], *pwbig[NL_], *pwout[NL_];
    static cudaStream_t s1;
    static cudaEvent_t evFork, evWh, evJoin;
    static cudaEvent_t evIn[NL_], evPP[NL_], evOw[NL_];
    if (!px) {
        cudaGetSymbolAddress((void**)&pxz,    g_xz);
        cudaGetSymbolAddress((void**)&pdtl,   g_dtl);
        cudaGetSymbolAddress((void**)&ptmp,   g_tmp);
        cudaGetSymbolAddress((void**)&pxh,    g_xh);
        cudaGetSymbolAddress((void**)&pxsh,   g_xsh);
        cudaGetSymbolAddress((void**)&pxdblh, g_xdblh);
        cudaGetSymbolAddress((void**)&pyh,    g_yh);
        cudaGetSymbolAddress((void**)&pwh,    g_wh);
        __half* hb;
        cudaGetSymbolAddress((void**)&hb, g_wpad);
        for (int L = 0; L < NL_; L++) pwpad[L] = hb + (size_t)L * XDP * DI_;
        cudaGetSymbolAddress((void**)&hb, g_dtwpad);
        for (int L = 0; L < NL_; L++) pdtw[L] = hb + (size_t)L * DI_ * 64;
        cudaGetSymbolAddress((void**)&hb, g_wbig);
        for (int L = 0; L < NL_; L++) pwbig[L] = hb + (size_t)L * 2 * DI_ * D_MODEL;
        cudaGetSymbolAddress((void**)&hb, g_wout);
        for (int L = 0; L < NL_; L++) pwout[L] = hb + (size_t)L * D_MODEL * DI_;
        cudaFuncSetAttribute(gemm_s<0>,
                             cudaFuncAttributeMaxDynamicSharedMemorySize, SMEM_GS);
        cudaFuncSetAttribute(gemm_s<1>,
                             cudaFuncAttributeMaxDynamicSharedMemorySize, SMEM_GS);
        cudaFuncSetAttribute(gemm_s<2>,
                             cudaFuncAttributeMaxDynamicSharedMemorySize, SMEM_GS);
        cudaStreamCreateWithFlags(&s1, cudaStreamNonBlocking);
        cudaEventCreateWithFlags(&evFork, cudaEventDisableTiming);
        cudaEventCreateWithFlags(&evWh,   cudaEventDisableTiming);
        cudaEventCreateWithFlags(&evJoin, cudaEventDisableTiming);
        for (int L = 0; L < NL_; L++) {
            cudaEventCreateWithFlags(&evIn[L], cudaEventDisableTiming);
            cudaEventCreateWithFlags(&evPP[L], cudaEventDisableTiming);
            cudaEventCreateWithFlags(&evOw[L], cudaEventDisableTiming);
        }
        cudaGetSymbolAddress((void**)&px, g_x);
    }

    cudaEventRecord(evFork, 0);
    cudaStreamWaitEvent(s1, evFork, 0);

    embed_kernel<<<(S_LEN * D_MODEL + 255) / 256, 256>>>(tokens, emb);          // idx 0

    roundcopy_h<<<(2 * DI_ * D_MODEL / 4 + 255) / 256, 256, 0, s1>>>(           // idx 1
        (__half2*)pwbig[0], (const float4*)in_w, 2 * DI_ * D_MODEL / 4);
    cudaEventRecord(evIn[0], s1);
    padw_kernel<<<(XDP * DI_ + 255) / 256, 256, 0, s1>>>(xproj_w, 0);           // idx 2

    // in-proj L0 (profiled launch idx 3)
    cudaStreamWaitEvent(0, evIn[0], 0);
    gemm_s<0><<<dim3(S_LEN / 64, 2 * DI_ / 64), 128, SMEM_GS>>>(
        pxh, pwbig[0], pxz, D_MODEL, D_MODEL, D_MODEL, 2 * DI_, nullptr);       // idx 3

    paddt_kernel<<<(DI_ * 64 + 255) / 256, 256, 0, s1>>>(dt_w, 0);
    cudaEventRecord(evPP[0], s1);
    roundcopy_h<<<(D_MODEL * DI_ / 4 + 255) / 256, 256, 0, s1>>>(
        (__half2*)pwout[0], (const float4*)out_w, D_MODEL * DI_ / 4);
    cudaEventRecord(evOw[0], s1);
    roundcopy_h<<<(2 * DI_ * D_MODEL / 4 + 255) / 256, 256, 0, s1>>>(
        (__half2*)pwbig[1], (const float4*)(in_w + (size_t)2 * DI_ * D_MODEL),
        2 * DI_ * D_MODEL / 4);
    cudaEventRecord(evIn[1], s1);
    padw_kernel<<<(XDP * DI_ + 255) / 256, 256, 0, s1>>>(xproj_w, 1);
    paddt_kernel<<<(DI_ * 64 + 255) / 256, 256, 0, s1>>>(dt_w, 1);
    cudaEventRecord(evPP[1], s1);
    roundcopy_h<<<(D_MODEL * DI_ / 4 + 255) / 256, 256, 0, s1>>>(
        (__half2*)pwout[1], (const float4*)(out_w + (size_t)D_MODEL * DI_),
        D_MODEL * DI_ / 4);
    cudaEventRecord(evOw[1], s1);
    roundcopy_h<<<(VOCAB * D_MODEL / 4 + 255) / 256, 256, 0, s1>>>(
        (__half2*)pwh, (const float4*)head_w, VOCAB * D_MODEL / 4);
    cudaEventRecord(evWh, s1);
    cudaEventRecord(evJoin, s1);

    for (int L = 0; L < NL_; L++) {
        if (L > 0) {
            cudaStreamWaitEvent(0, evIn[L], 0);
            gemm_s<0><<<dim3(S_LEN / 64, 2 * DI_ / 64), 128, SMEM_GS>>>(
                pxh, pwbig[L], pxz, D_MODEL, D_MODEL, D_MODEL, 2 * DI_, nullptr);
        }
        conv_silu_kernel<<<(S_LEN * DI_ + 255) / 256, 256>>>(conv_w, conv_b, L);

        cudaStreamWaitEvent(0, evPP[L], 0);
        gemm_s<1><<<dim3(S_LEN / 64, XDP / 64), 128, SMEM_GS>>>(
            pxsh, pwpad[L], pxdblh, DI_, DI_, DI_, XDP, nullptr);
        gemm_s<2><<<dim3(S_LEN / 64, DI_ / 64), 128, SMEM_GS>>>(
            pxdblh, pdtw[L], pdtl, 64, XDP, 64, DI_, dt_b + (size_t)L * DI_);

        bump_epoch<<<1, 1>>>();
        scan_fused<<<dim3(DI_ / 128, NCHUNK), 128>>>(A_log, Dp, L);

        cudaStreamWaitEvent(0, evOw[L], 0);
        gemm_s<0><<<dim3(S_LEN / 64, D_MODEL / 64), 128, SMEM_GS>>>(
            pyh, pwout[L], ptmp, DI_, DI_, DI_, D_MODEL, nullptr);

        ln_kernel<<<S_LEN, 256>>>(ln_g, ln_b, L);
    }

    cudaStreamWaitEvent(0, evWh, 0);
    cudaStreamWaitEvent(0, evJoin, 0);
    gemm_s<0><<<dim3(S_LEN / 64, VOCAB / 64), 128, SMEM_GS>>>(
        pxh, pwh, out, D_MODEL, D_MODEL, D_MODEL, VOCAB, nullptr);
}

// round 14
// speedup vs baseline: 1.1129x; 1.0075x over previous
#include <cuda_runtime.h>
#include <cuda_fp16.h>
#include <cstdint>
#include <math.h>

#define S_LEN   1024
#define D_MODEL 768
#define DI_     1536
#define N_ST    16
#define K_CONV  4
#define DTRANK  48
#define XDP     128
#define VOCAB   32000
#define NL_     2
#define NCHUNK  32
#define CLEN    32
#define GROUPS  (DI_ * N_ST)

// ---------------- scratch ----------------
__device__ __align__(128) float  g_x    [S_LEN * D_MODEL];
__device__ __align__(128) __half g_xh   [S_LEN * D_MODEL];
__device__ __align__(128) __half g_xz   [S_LEN * 2 * DI_];   // now half
__device__ __align__(128) __half g_xsh  [S_LEN * DI_];
__device__ __align__(128) __half g_xdblh[S_LEN * XDP];
__device__ __align__(128) float  g_dtl  [S_LEN * DI_];
__device__ __align__(128) __half g_yh   [S_LEN * DI_];
__device__ __align__(128) float  g_tmp  [S_LEN * D_MODEL];
__device__ __align__(128) __half g_wpad  [NL_][XDP * DI_];
__device__ __align__(128) __half g_dtwpad[NL_][DI_ * 64];
__device__ __align__(128) __half g_wbig  [NL_][2 * DI_ * D_MODEL];
__device__ __align__(128) __half g_wout  [NL_][D_MODEL * DI_];
__device__ __align__(128) __half g_wh    [VOCAB * D_MODEL];
__device__ __align__(128) float  g_P  [NCHUNK * GROUPS];
__device__ __align__(128) float  g_H  [NCHUNK * GROUPS];
__device__ __align__(128) float  g_I  [NCHUNK * GROUPS];
__device__ int g_flag [NCHUNK * DI_];
__device__ int g_epoch;

// ---------------- helpers ----------------
__device__ __forceinline__ uint32_t smem_u32(const void* p) {
    uint32_t a;
    asm("{ .reg .u64 t; cvta.to.shared.u64 t, %1; cvt.u32.u64 %0, t; }" : "=r"(a) : "l"(p));
    return a;
}
__device__ __forceinline__ float silu_f(float x) { return x / (1.0f + __expf(-x)); }
__device__ __forceinline__ float sp_f(float a)   { return (a > 20.0f) ? a : log1pf(__expf(a)); }

#define CP_ASYNC16(dst, src) \
    asm volatile("cp.async.cg.shared.global [%0], [%1], 16;" :: "r"(dst), "l"(src))
#define CP_COMMIT() asm volatile("cp.async.commit_group;" ::: "memory")
#define CP_WAIT(n)  asm volatile("cp.async.wait_group %0;" :: "n"(n) : "memory")
#define LDSM4(d0, d1, d2, d3, a) \
    asm volatile("ldmatrix.sync.aligned.m8n8.x4.shared.b16 {%0,%1,%2,%3}, [%4];" \
        : "=r"(d0), "=r"(d1), "=r"(d2), "=r"(d3) : "r"(a))

__device__ __forceinline__ void mma_f16(float* c, const uint32_t* a, const uint32_t* b) {
    asm volatile(
        "mma.sync.aligned.m16n8k16.row.col.f32.f16.f16.f32 "
        "{%0,%1,%2,%3}, {%4,%5,%6,%7}, {%8,%9}, {%0,%1,%2,%3};"
        : "+f"(c[0]), "+f"(c[1]), "+f"(c[2]), "+f"(c[3])
        : "r"(a[0]), "r"(a[1]), "r"(a[2]), "r"(a[3]), "r"(b[0]), "r"(b[1]));
}

// ---------------- fp16 GEMM: 64x64, 4 warps, 3-stage, 4 CTAs/SM ---------------
#define STG_S 8192
#define SMEM_GS (3 * 2 * STG_S)

template<int OM>   // 0 fp32 out, 1 half out, 2 fp32 softplus(acc+bias) out
__global__ __launch_bounds__(128, 4)
void gemm_s(const __half* __restrict__ A, const __half* __restrict__ B,
            void* __restrict__ Cv, int K, int lda, int ldb, int ldc,
            const float* __restrict__ bias)
{
    extern __shared__ char smem[];
    const int tid = threadIdx.x, lane = tid & 31, wid = tid >> 5;
    const int wm = wid >> 1, wn = wid & 1;
    const int bm = blockIdx.x * 64, bn = blockIdx.y * 64;
    const int nc = K >> 6;
    const int lr = lane & 7, lg = lane >> 3;

    const uint32_t sb = smem_u32(smem);
    const __half* Ab = A + (size_t)bm * lda;
    const __half* Bb = B + (size_t)bn * ldb;

    auto loadA = [&](int chunk, int st) {
        uint32_t d0 = sb + st * (2 * STG_S);
        const __half* s0 = Ab + chunk * 64;
#pragma unroll
        for (int it = 0; it < 4; it++) {
            int i = tid + it * 128;
            int r = i >> 3, q = i & 7;
            uint32_t off = ((uint32_t)r << 7) | (((uint32_t)q << 4) ^ (((uint32_t)(r & 7)) << 4));
            CP_ASYNC16(d0 + off, s0 + (size_t)r * lda + q * 8);
        }
    };
    auto loadB = [&](int chunk, int st) {
        uint32_t d0 = sb + st * (2 * STG_S) + STG_S;
        const __half* s0 = Bb + chunk * 64;
#pragma unroll
        for (int it = 0; it < 4; it++) {
            int i = tid + it * 128;
            int r = i >> 3, q = i & 7;
            uint32_t off = ((uint32_t)r << 7) | (((uint32_t)q << 4) ^ (((uint32_t)(r & 7)) << 4));
            CP_ASYNC16(d0 + off, s0 + (size_t)r * ldb + q * 8);
        }
    };

    const int a_row0 = wm * 32 + ((lg & 1) << 3) + lr;
    const int a_coff = (lg >> 1) << 4;
    const int b_row0 = wn * 32 + ((lg & 2) << 2) + lr;
    const int b_coff = (lg & 1) << 4;
    const uint32_t sw = (uint32_t)lr << 4;

    float acc[2][4][4];
#pragma unroll
    for (int i = 0; i < 2; i++)
#pragma unroll
        for (int j = 0; j < 4; j++)
#pragma unroll
            for (int v = 0; v < 4; v++) acc[i][j][v] = 0.0f;

    int npre = nc < 2 ? nc : 2;
    for (int c = 0; c < npre; c++) { loadA(c, c); loadB(c, c); CP_COMMIT(); }

    for (int i = 0; i < nc; i++) {
        if (i + 2 < nc) { CP_WAIT(1); } else { CP_WAIT(0); }
        __syncthreads();
        if (i + 2 < nc) {
            int s2 = (i + 2) % 3;
            loadA(i + 2, s2); loadB(i + 2, s2); CP_COMMIT();
        }
        uint32_t abase = sb + (i % 3) * (2 * STG_S);
        uint32_t bbase = abase + STG_S;
#pragma unroll
        for (int ks = 0; ks < 4; ks++) {
            const uint32_t kb = (uint32_t)ks * 32;
            uint32_t afr[2][4];
#pragma unroll
            for (int mf = 0; mf < 2; mf++) {
                uint32_t ad = abase + (uint32_t)(a_row0 + mf * 16) * 128 + ((kb + a_coff) ^ sw);
                LDSM4(afr[mf][0], afr[mf][1], afr[mf][2], afr[mf][3], ad);
            }
            uint32_t bfr[4][2];
#pragma unroll
            for (int p = 0; p < 2; p++) {
                uint32_t bd = bbase + (uint32_t)(b_row0 + p * 16) * 128 + ((kb + b_coff) ^ sw);
                LDSM4(bfr[2 * p][0], bfr[2 * p][1], bfr[2 * p + 1][0], bfr[2 * p + 1][1], bd);
            }
#pragma unroll
            for (int mf = 0; mf < 2; mf++)
#pragma unroll
                for (int nf = 0; nf < 4; nf++)
                    mma_f16(acc[mf][nf], afr[mf], bfr[nf]);
        }
    }

#pragma unroll
    for (int mf = 0; mf < 2; mf++) {
        int row = bm + wm * 32 + mf * 16 + (lane >> 2);
#pragma unroll
        for (int nf = 0; nf < 4; nf++) {
            int col = bn + wn * 32 + nf * 8 + 2 * (lane & 3);
            if (OM == 1) {
                __half* C = (__half*)Cv;
                *(__half2*)(C + (size_t)row * ldc + col) =
                    __floats2half2_rn(acc[mf][nf][0], acc[mf][nf][1]);
                *(__half2*)(C + (size_t)(row + 8) * ldc + col) =
                    __floats2half2_rn(acc[mf][nf][2], acc[mf][nf][3]);
            } else if (OM == 2) {
                float* C = (float*)Cv;
                float b0 = bias[col], b1 = bias[col + 1];
                *(float2*)(C + (size_t)row * ldc + col) =
                    make_float2(sp_f(acc[mf][nf][0] + b0), sp_f(acc[mf][nf][1] + b1));
                *(float2*)(C + (size_t)(row + 8) * ldc + col) =
                    make_float2(sp_f(acc[mf][nf][2] + b0), sp_f(acc[mf][nf][3] + b1));
            } else {
                float* C = (float*)Cv;
                *(float2*)(C + (size_t)row * ldc + col) =
                    make_float2(acc[mf][nf][0], acc[mf][nf][1]);
                *(float2*)(C + (size_t)(row + 8) * ldc + col) =
                    make_float2(acc[mf][nf][2], acc[mf][nf][3]);
            }
        }
    }
}

// ---------------- elementwise / small kernels ----------------
__global__ void roundcopy_h(__half2* __restrict__ dst, const float4* __restrict__ src, int n4) {
    int i = blockIdx.x * blockDim.x + threadIdx.x;
    if (i < n4) {
        float4 v = src[i];
        dst[2 * i]     = __floats2half2_rn(v.x, v.y);
        dst[2 * i + 1] = __floats2half2_rn(v.z, v.w);
    }
}

__global__ void embed_kernel(const int* __restrict__ tokens,
                             const float* __restrict__ emb) {
    int i = blockIdx.x * blockDim.x + threadIdx.x;
    if (i < S_LEN * D_MODEL) {
        int l = i / D_MODEL, d = i - l * D_MODEL;
        float e = emb[(size_t)tokens[l] * D_MODEL + d];
        g_x[i]  = e;
        g_xh[i] = __float2half_rn(e);
    }
}

__global__ void padw_kernel(const float* __restrict__ xw, int L) {
    int i = blockIdx.x * 256 + threadIdx.x;
    if (i >= XDP * DI_) return;
    int row = i / DI_, col = i - row * DI_;
    g_wpad[L][i] = (row < 80) ? __float2half_rn(xw[((size_t)L * 80 + row) * DI_ + col])
                              : __half(0.0f);
}

__global__ void paddt_kernel(const float* __restrict__ dw, int L) {
    int i = blockIdx.x * 256 + threadIdx.x;
    if (i >= DI_ * 64) return;
    int row = i >> 6, col = i & 63;
    g_dtwpad[L][i] = (col < DTRANK) ? __float2half_rn(dw[((size_t)L * DI_ + row) * DTRANK + col])
                                    : __half(0.0f);
}

// conv+silu, half2-vectorized (2 channels/thread); block 0 thread 0 bumps epoch
__global__ void conv_silu_kernel(const float* __restrict__ conv_w,
                                 const float* __restrict__ conv_b, int layer) {
    if (blockIdx.x == 0 && threadIdx.x == 0) atomicAdd(&g_epoch, 1);
    int i = blockIdx.x * blockDim.x + threadIdx.x;     // pair index
    if (i >= S_LEN * DI_ / 2) return;
    int t = i / (DI_ / 2), cp = i - t * (DI_ / 2);
    int c = cp * 2;
    const float* w0 = conv_w + ((size_t)layer * DI_ + c) * K_CONV;
    const float* w1 = w0 + K_CONV;
    float a0 = conv_b[layer * DI_ + c];
    float a1 = conv_b[layer * DI_ + c + 1];
#pragma unroll
    for (int k = 0; k < K_CONV; k++) {
        int tt = t - (K_CONV - 1) + k;
        if (tt >= 0) {
            float2 xv = __half22float2(
                *(const __half2*)(g_xz + (size_t)tt * 2 * DI_ + c));
            a0 += w0[k] * xv.x;
            a1 += w1[k] * xv.y;
        }
    }
    *(__half2*)(g_xsh + (size_t)t * DI_ + c) =
        __floats2half2_rn(silu_f(a0), silu_f(a1));
}

// ---------------- single-pass scan with decoupled look-back -------------------
__global__ __launch_bounds__(128)
void scan_fused(const float* __restrict__ A_log, const float* __restrict__ Dp,
                int layer) {
    const int c = blockIdx.x * 128 + threadIdx.x;
    const int j = blockIdx.y;
    const int e2 = 2 * (*(volatile int*)&g_epoch);
    const int t0 = j * CLEN;

    float Acn[N_ST];
#pragma unroll
    for (int n = 0; n < N_ST; n++)
        Acn[n] = -expf(A_log[((size_t)layer * DI_ + c) * N_ST + n]);

    float h[N_ST];
#pragma unroll
    for (int n = 0; n < N_ST; n++) h[n] = 0.0f;
    float yloc[CLEN];
    float Sdt = 0.0f;
#pragma unroll 4
    for (int tt = 0; tt < CLEN; tt++) {
        int t = t0 + tt;
        float dtv = g_dtl[(size_t)t * DI_ + c];
        float xv  = __half2float(g_xsh[(size_t)t * DI_ + c]);
        float dx  = dtv * xv;
        Sdt += dtv;
        const __half2* bc = (const __half2*)(g_xdblh + (size_t)t * XDP + DTRANK);
        float y = 0.0f;
#pragma unroll
        for (int q = 0; q < 8; q++) {
            float2 B2 = __half22float2(bc[q]);
            float2 C2 = __half22float2(bc[8 + q]);
            float dA0 = __expf(dtv * Acn[2 * q]);
            float dA1 = __expf(dtv * Acn[2 * q + 1]);
            h[2 * q]     = dA0 * h[2 * q]     + dx * B2.x;
            h[2 * q + 1] = dA1 * h[2 * q + 1] + dx * B2.y;
            y += h[2 * q] * C2.x + h[2 * q + 1] * C2.y;
        }
        yloc[tt] = y;
    }

    float Pself[N_ST];
#pragma unroll
    for (int n = 0; n < N_ST; n++) Pself[n] = __expf(Sdt * Acn[n]);

    {
        float* Hp = g_H + (size_t)j * GROUPS + (size_t)c * N_ST;
        float* Pp = g_P + (size_t)j * GROUPS + (size_t)c * N_ST;
#pragma unroll
        for (int n = 0; n < N_ST; n++) { __stcg(&Hp[n], h[n]); __stcg(&Pp[n], Pself[n]); }
        __threadfence();
        ((volatile int*)g_flag)[j * DI_ + c] = e2 + 1;
    }

    float carry[N_ST];
#pragma unroll
    for (int n = 0; n < N_ST; n++) carry[n] = 0.0f;
    if (j > 0) {
        float prod[N_ST];
#pragma unroll
        for (int n = 0; n < N_ST; n++) prod[n] = 1.0f;
        int jj = j - 1;
        while (true) {
            int f = ((volatile int*)g_flag)[jj * DI_ + c];
            while (f < e2 + 1) {
                __nanosleep(60);
                f = ((volatile int*)g_flag)[jj * DI_ + c];
            }
            __threadfence();
            if (f >= e2 + 2) {
                const float* Iq = g_I + (size_t)jj * GROUPS + (size_t)c * N_ST;
#pragma unroll
                for (int n = 0; n < N_ST; n++) carry[n] += prod[n] * __ldcg(&Iq[n]);
                break;
            }
            const float* Hq = g_H + (size_t)jj * GROUPS + (size_t)c * N_ST;
            const float* Pq = g_P + (size_t)jj * GROUPS + (size_t)c * N_ST;
#pragma unroll
            for (int n = 0; n < N_ST; n++) {
                carry[n] += prod[n] * __ldcg(&Hq[n]);
                prod[n]  *= __ldcg(&Pq[n]);
            }
            if (--jj < 0) break;
        }
    }

    {
        float* Iq = g_I + (size_t)j * GROUPS + (size_t)c * N_ST;
#pragma unroll
        for (int n = 0; n < N_ST; n++) __stcg(&Iq[n], h[n] + Pself[n] * carry[n]);
        __threadfence();
        ((volatile int*)g_flag)[j * DI_ + c] = e2 + 2;
    }

    float Dpc = Dp[layer * DI_ + c];
    if (j == 0) {
#pragma unroll 4
        for (int tt = 0; tt < CLEN; tt++) {
            int t = t0 + tt;
            float xv = __half2float(g_xsh[(size_t)t * DI_ + c]);
            float z  = __half2float(g_xz[(size_t)t * 2 * DI_ + DI_ + c]);
            g_yh[(size_t)t * DI_ + c] = __float2half_rn(
                (yloc[tt] + xv * Dpc) * silu_f(z));
        }
    } else {
        float S = 0.0f;
#pragma unroll 4
        for (int tt = 0; tt < CLEN; tt++) {
            int t = t0 + tt;
            float dtv = g_dtl[(size_t)t * DI_ + c];
            S += dtv;
            const __half2* cc = (const __half2*)(g_xdblh + (size_t)t * XDP + DTRANK + N_ST);
            float v = 0.0f;
#pragma unroll
            for (int q = 0; q < 8; q++) {
                float2 C2 = __half22float2(cc[q]);
                v += C2.x * __expf(S * Acn[2 * q])     * carry[2 * q];
                v += C2.y * __expf(S * Acn[2 * q + 1]) * carry[2 * q + 1];
            }
            float xv = __half2float(g_xsh[(size_t)t * DI_ + c]);
            float z  = __half2float(g_xz[(size_t)t * 2 * DI_ + DI_ + c]);
            g_yh[(size_t)t * DI_ + c] = __float2half_rn(
                (yloc[tt] + v + xv * Dpc) * silu_f(z));
        }
    }
}

__global__ __launch_bounds__(256)
void ln_kernel(const float* __restrict__ gam, const float* __restrict__ bet, int layer) {
    int l = blockIdx.x;
    __shared__ float rsum[8], rsq[8];
    float sum = 0.0f, sq = 0.0f;
    for (int d = threadIdx.x; d < D_MODEL; d += 256) {
        float v = g_x[(size_t)l * D_MODEL + d] + g_tmp[(size_t)l * D_MODEL + d];
        sum += v; sq += v * v;
    }
#pragma unroll
    for (int o = 16; o > 0; o >>= 1) {
        sum += __shfl_down_sync(0xffffffffu, sum, o);
        sq  += __shfl_down_sync(0xffffffffu, sq, o);
    }
    int wid = threadIdx.x >> 5;
    if ((threadIdx.x & 31) == 0) { rsum[wid] = sum; rsq[wid] = sq; }
    __syncthreads();
    if (threadIdx.x == 0) {
        float s = 0.0f, q = 0.0f;
#pragma unroll
        for (int w = 0; w < 8; w++) { s += rsum[w]; q += rsq[w]; }
        rsum[0] = s; rsq[0] = q;
    }
    __syncthreads();
    float mu  = rsum[0] / (float)D_MODEL;
    float var = rsq[0] / (float)D_MODEL - mu * mu;
    float rinv = rsqrtf(var + 1e-5f);
    for (int d = threadIdx.x; d < D_MODEL; d += 256) {
        float v = g_x[(size_t)l * D_MODEL + d] + g_tmp[(size_t)l * D_MODEL + d];
        float o = (v - mu) * rinv * gam[layer * D_MODEL + d] + bet[layer * D_MODEL + d];
        g_x [(size_t)l * D_MODEL + d] = o;
        g_xh[(size_t)l * D_MODEL + d] = __float2half_rn(o);
    }
}

// ---------------- launch ----------------
extern "C" void kernel_launch(void* const* d_in, const int* in_sizes, int n_in,
                              void* d_out, int out_size) {
    const int*   tokens  = (const int*)  d_in[0];
    const float* emb     = (const float*)d_in[1];
    const float* in_w    = (const float*)d_in[2];
    const float* conv_w  = (const float*)d_in[3];
    const float* conv_b  = (const float*)d_in[4];
    const float* xproj_w = (const float*)d_in[5];
    const float* dt_w    = (const float*)d_in[6];
    const float* dt_b    = (const float*)d_in[7];
    const float* A_log   = (const float*)d_in[8];
    const float* Dp      = (const float*)d_in[9];
    const float* out_w   = (const float*)d_in[10];
    const float* ln_g    = (const float*)d_in[11];
    const float* ln_b    = (const float*)d_in[12];
    const float* head_w  = (const float*)d_in[13];
    float* out = (float*)d_out;

    static float *px = nullptr, *pdtl, *ptmp;
    static __half *pxh, *pxz, *pxsh, *pxdblh, *pyh, *pwh;
    static __half *pwpad[NL_], *pdtw[NL_], *pwbig[NL_], *pwout[NL_];
    static cudaStream_t s1;
    static cudaEvent_t evFork, evWh, evJoin;
    static cudaEvent_t evIn[NL_], evPP[NL_], evOw[NL_];
    if (!px) {
        cudaGetSymbolAddress((void**)&pxz,    g_xz);
        cudaGetSymbolAddress((void**)&pdtl,   g_dtl);
        cudaGetSymbolAddress((void**)&ptmp,   g_tmp);
        cudaGetSymbolAddress((void**)&pxh,    g_xh);
        cudaGetSymbolAddress((void**)&pxsh,   g_xsh);
        cudaGetSymbolAddress((void**)&pxdblh, g_xdblh);
        cudaGetSymbolAddress((void**)&pyh,    g_yh);
        cudaGetSymbolAddress((void**)&pwh,    g_wh);
        __half* hb;
        cudaGetSymbolAddress((void**)&hb, g_wpad);
        for (int L = 0; L < NL_; L++) pwpad[L] = hb + (size_t)L * XDP * DI_;
        cudaGetSymbolAddress((void**)&hb, g_dtwpad);
        for (int L = 0; L < NL_; L++) pdtw[L] = hb + (size_t)L * DI_ * 64;
        cudaGetSymbolAddress((void**)&hb, g_wbig);
        for (int L = 0; L < NL_; L++) pwbig[L] = hb + (size_t)L * 2 * DI_ * D_MODEL;
        cudaGetSymbolAddress((void**)&hb, g_wout);
        for (int L = 0; L < NL_; L++) pwout[L] = hb + (size_t)L * D_MODEL * DI_;
        cudaFuncSetAttribute(gemm_s<0>,
                             cudaFuncAttributeMaxDynamicSharedMemorySize, SMEM_GS);
        cudaFuncSetAttribute(gemm_s<1>,
                             cudaFuncAttributeMaxDynamicSharedMemorySize, SMEM_GS);
        cudaFuncSetAttribute(gemm_s<2>,
                             cudaFuncAttributeMaxDynamicSharedMemorySize, SMEM_GS);
        cudaStreamCreateWithFlags(&s1, cudaStreamNonBlocking);
        cudaEventCreateWithFlags(&evFork, cudaEventDisableTiming);
        cudaEventCreateWithFlags(&evWh,   cudaEventDisableTiming);
        cudaEventCreateWithFlags(&evJoin, cudaEventDisableTiming);
        for (int L = 0; L < NL_; L++) {
            cudaEventCreateWithFlags(&evIn[L], cudaEventDisableTiming);
            cudaEventCreateWithFlags(&evPP[L], cudaEventDisableTiming);
            cudaEventCreateWithFlags(&evOw[L], cudaEventDisableTiming);
        }
        cudaGetSymbolAddress((void**)&px, g_x);
    }

    cudaEventRecord(evFork, 0);
    cudaStreamWaitEvent(s1, evFork, 0);

    embed_kernel<<<(S_LEN * D_MODEL + 255) / 256, 256>>>(tokens, emb);          // idx 0

    roundcopy_h<<<(2 * DI_ * D_MODEL / 4 + 255) / 256, 256, 0, s1>>>(           // idx 1
        (__half2*)pwbig[0], (const float4*)in_w, 2 * DI_ * D_MODEL / 4);
    cudaEventRecord(evIn[0], s1);
    padw_kernel<<<(XDP * DI_ + 255) / 256, 256, 0, s1>>>(xproj_w, 0);           // idx 2

    // in-proj L0 (profiled launch idx 3), half output into g_xz
    cudaStreamWaitEvent(0, evIn[0], 0);
    gemm_s<1><<<dim3(S_LEN / 64, 2 * DI_ / 64), 128, SMEM_GS>>>(
        pxh, pwbig[0], pxz, D_MODEL, D_MODEL, D_MODEL, 2 * DI_, nullptr);       // idx 3

    paddt_kernel<<<(DI_ * 64 + 255) / 256, 256, 0, s1>>>(dt_w, 0);
    cudaEventRecord(evPP[0], s1);
    roundcopy_h<<<(D_MODEL * DI_ / 4 + 255) / 256, 256, 0, s1>>>(
        (__half2*)pwout[0], (const float4*)out_w, D_MODEL * DI_ / 4);
    cudaEventRecord(evOw[0], s1);
    roundcopy_h<<<(2 * DI_ * D_MODEL / 4 + 255) / 256, 256, 0, s1>>>(
        (__half2*)pwbig[1], (const float4*)(in_w + (size_t)2 * DI_ * D_MODEL),
        2 * DI_ * D_MODEL / 4);
    cudaEventRecord(evIn[1], s1);
    padw_kernel<<<(XDP * DI_ + 255) / 256, 256, 0, s1>>>(xproj_w, 1);
    paddt_kernel<<<(DI_ * 64 + 255) / 256, 256, 0, s1>>>(dt_w, 1);
    cudaEventRecord(evPP[1], s1);
    roundcopy_h<<<(D_MODEL * DI_ / 4 + 255) / 256, 256, 0, s1>>>(
        (__half2*)pwout[1], (const float4*)(out_w + (size_t)D_MODEL * DI_),
        D_MODEL * DI_ / 4);
    cudaEventRecord(evOw[1], s1);
    roundcopy_h<<<(VOCAB * D_MODEL / 4 + 255) / 256, 256, 0, s1>>>(
        (__half2*)pwh, (const float4*)head_w, VOCAB * D_MODEL / 4);
    cudaEventRecord(evWh, s1);
    cudaEventRecord(evJoin, s1);

    for (int L = 0; L < NL_; L++) {
        if (L > 0) {
            cudaStreamWaitEvent(0, evIn[L], 0);
            gemm_s<1><<<dim3(S_LEN / 64, 2 * DI_ / 64), 128, SMEM_GS>>>(
                pxh, pwbig[L], pxz, D_MODEL, D_MODEL, D_MODEL, 2 * DI_, nullptr);
        }
        conv_silu_kernel<<<(S_LEN * DI_ / 2 + 255) / 256, 256>>>(conv_w, conv_b, L);

        cudaStreamWaitEvent(0, evPP[L], 0);
        gemm_s<1><<<dim3(S_LEN / 64, XDP / 64), 128, SMEM_GS>>>(
            pxsh, pwpad[L], pxdblh, DI_, DI_, DI_, XDP, nullptr);
        gemm_s<2><<<dim3(S_LEN / 64, DI_ / 64), 128, SMEM_GS>>>(
            pxdblh, pdtw[L], pdtl, 64, XDP, 64, DI_, dt_b + (size_t)L * DI_);

        scan_fused<<<dim3(DI_ / 128, NCHUNK), 128>>>(A_log, Dp, L);

        cudaStreamWaitEvent(0, evOw[L], 0);
        gemm_s<0><<<dim3(S_LEN / 64, D_MODEL / 64), 128, SMEM_GS>>>(
            pyh, pwout[L], ptmp, DI_, DI_, DI_, D_MODEL, nullptr);

        ln_kernel<<<S_LEN, 256>>>(ln_g, ln_b, L);
    }

    cudaStreamWaitEvent(0, evWh, 0);
    cudaStreamWaitEvent(0, evJoin, 0);
    gemm_s<0><<<dim3(S_LEN / 64, VOCAB / 64), 128, SMEM_GS>>>(
        pxh, pwh, out, D_MODEL, D_MODEL, D_MODEL, VOCAB, nullptr);
}

// round 15
// speedup vs baseline: 1.1451x; 1.0290x over previous
#include <cuda_runtime.h>
#include <cuda_fp16.h>
#include <cstdint>
#include <math.h>

#define S_LEN   1024
#define D_MODEL 768
#define DI_     1536
#define N_ST    16
#define K_CONV  4
#define DTRANK  48
#define XDP     128
#define VOCAB   32000
#define NL_     2
#define NCHUNK  32
#define CLEN    32
#define GROUPS  (DI_ * N_ST)

// ---------------- scratch ----------------
__device__ __align__(128) float  g_x    [S_LEN * D_MODEL];
__device__ __align__(128) __half g_xh   [S_LEN * D_MODEL];
__device__ __align__(128) __half g_xz   [S_LEN * 2 * DI_];
__device__ __align__(128) __half g_xsh  [S_LEN * DI_];
__device__ __align__(128) __half g_xdblh[S_LEN * XDP];
__device__ __align__(128) float  g_dtl  [S_LEN * DI_];
__device__ __align__(128) __half g_yh   [S_LEN * DI_];
__device__ __align__(128) float  g_tmp  [S_LEN * D_MODEL];
__device__ __align__(128) __half g_wpad  [NL_][XDP * DI_];
__device__ __align__(128) __half g_dtwpad[NL_][DI_ * 64];
__device__ __align__(128) __half g_wbig  [NL_][2 * DI_ * D_MODEL];
__device__ __align__(128) __half g_wout  [NL_][D_MODEL * DI_];
__device__ __align__(128) __half g_wh    [VOCAB * D_MODEL];
__device__ __align__(128) float  g_P  [NCHUNK * GROUPS];
__device__ __align__(128) float  g_H  [NCHUNK * GROUPS];
__device__ __align__(128) float  g_I  [NCHUNK * GROUPS];
__device__ int g_flag [NCHUNK * DI_];
__device__ int g_epoch;

// ---------------- helpers ----------------
__device__ __forceinline__ uint32_t smem_u32(const void* p) {
    uint32_t a;
    asm("{ .reg .u64 t; cvta.to.shared.u64 t, %1; cvt.u32.u64 %0, t; }" : "=r"(a) : "l"(p));
    return a;
}
__device__ __forceinline__ float silu_f(float x) { return x / (1.0f + __expf(-x)); }
__device__ __forceinline__ float sp_f(float a)   { return (a > 20.0f) ? a : log1pf(__expf(a)); }

#define CP_ASYNC16(dst, src) \
    asm volatile("cp.async.cg.shared.global [%0], [%1], 16;" :: "r"(dst), "l"(src))
#define CP_COMMIT() asm volatile("cp.async.commit_group;" ::: "memory")
#define CP_WAIT(n)  asm volatile("cp.async.wait_group %0;" :: "n"(n) : "memory")
#define LDSM4(d0, d1, d2, d3, a) \
    asm volatile("ldmatrix.sync.aligned.m8n8.x4.shared.b16 {%0,%1,%2,%3}, [%4];" \
        : "=r"(d0), "=r"(d1), "=r"(d2), "=r"(d3) : "r"(a))

__device__ __forceinline__ void mma_f16(float* c, const uint32_t* a, const uint32_t* b) {
    asm volatile(
        "mma.sync.aligned.m16n8k16.row.col.f32.f16.f16.f32 "
        "{%0,%1,%2,%3}, {%4,%5,%6,%7}, {%8,%9}, {%0,%1,%2,%3};"
        : "+f"(c[0]), "+f"(c[1]), "+f"(c[2]), "+f"(c[3])
        : "r"(a[0]), "r"(a[1]), "r"(a[2]), "r"(a[3]), "r"(b[0]), "r"(b[1]));
}

// ---------------- gemm_s: 64x64, 4 warps (32x32), 3-stage, 4 CTAs/SM ----------
#define STG_S 8192
#define SMEM_GS (3 * 2 * STG_S)

template<int OM>   // 0 fp32 out, 1 half out, 2 fp32 softplus(acc+bias) out
__global__ __launch_bounds__(128, 4)
void gemm_s(const __half* __restrict__ A, const __half* __restrict__ B,
            void* __restrict__ Cv, int K, int lda, int ldb, int ldc,
            const float* __restrict__ bias)
{
    extern __shared__ char smem[];
    const int tid = threadIdx.x, lane = tid & 31, wid = tid >> 5;
    const int wm = wid >> 1, wn = wid & 1;
    const int bm = blockIdx.x * 64, bn = blockIdx.y * 64;
    const int nc = K >> 6;
    const int lr = lane & 7, lg = lane >> 3;

    const uint32_t sb = smem_u32(smem);
    const __half* Ab = A + (size_t)bm * lda;
    const __half* Bb = B + (size_t)bn * ldb;

    auto loadA = [&](int chunk, int st) {
        uint32_t d0 = sb + st * (2 * STG_S);
        const __half* s0 = Ab + chunk * 64;
#pragma unroll
        for (int it = 0; it < 4; it++) {
            int i = tid + it * 128;
            int r = i >> 3, q = i & 7;
            uint32_t off = ((uint32_t)r << 7) | (((uint32_t)q << 4) ^ (((uint32_t)(r & 7)) << 4));
            CP_ASYNC16(d0 + off, s0 + (size_t)r * lda + q * 8);
        }
    };
    auto loadB = [&](int chunk, int st) {
        uint32_t d0 = sb + st * (2 * STG_S) + STG_S;
        const __half* s0 = Bb + chunk * 64;
#pragma unroll
        for (int it = 0; it < 4; it++) {
            int i = tid + it * 128;
            int r = i >> 3, q = i & 7;
            uint32_t off = ((uint32_t)r << 7) | (((uint32_t)q << 4) ^ (((uint32_t)(r & 7)) << 4));
            CP_ASYNC16(d0 + off, s0 + (size_t)r * ldb + q * 8);
        }
    };

    const int a_row0 = wm * 32 + ((lg & 1) << 3) + lr;
    const int a_coff = (lg >> 1) << 4;
    const int b_row0 = wn * 32 + ((lg & 2) << 2) + lr;
    const int b_coff = (lg & 1) << 4;
    const uint32_t sw = (uint32_t)lr << 4;

    float acc[2][4][4];
#pragma unroll
    for (int i = 0; i < 2; i++)
#pragma unroll
        for (int j = 0; j < 4; j++)
#pragma unroll
            for (int v = 0; v < 4; v++) acc[i][j][v] = 0.0f;

    int npre = nc < 2 ? nc : 2;
    for (int c = 0; c < npre; c++) { loadA(c, c); loadB(c, c); CP_COMMIT(); }

    for (int i = 0; i < nc; i++) {
        if (i + 2 < nc) { CP_WAIT(1); } else { CP_WAIT(0); }
        __syncthreads();
        if (i + 2 < nc) {
            int s2 = (i + 2) % 3;
            loadA(i + 2, s2); loadB(i + 2, s2); CP_COMMIT();
        }
        uint32_t abase = sb + (i % 3) * (2 * STG_S);
        uint32_t bbase = abase + STG_S;
#pragma unroll
        for (int ks = 0; ks < 4; ks++) {
            const uint32_t kb = (uint32_t)ks * 32;
            uint32_t afr[2][4];
#pragma unroll
            for (int mf = 0; mf < 2; mf++) {
                uint32_t ad = abase + (uint32_t)(a_row0 + mf * 16) * 128 + ((kb + a_coff) ^ sw);
                LDSM4(afr[mf][0], afr[mf][1], afr[mf][2], afr[mf][3], ad);
            }
            uint32_t bfr[4][2];
#pragma unroll
            for (int p = 0; p < 2; p++) {
                uint32_t bd = bbase + (uint32_t)(b_row0 + p * 16) * 128 + ((kb + b_coff) ^ sw);
                LDSM4(bfr[2 * p][0], bfr[2 * p][1], bfr[2 * p + 1][0], bfr[2 * p + 1][1], bd);
            }
#pragma unroll
            for (int mf = 0; mf < 2; mf++)
#pragma unroll
                for (int nf = 0; nf < 4; nf++)
                    mma_f16(acc[mf][nf], afr[mf], bfr[nf]);
        }
    }

#pragma unroll
    for (int mf = 0; mf < 2; mf++) {
        int row = bm + wm * 32 + mf * 16 + (lane >> 2);
#pragma unroll
        for (int nf = 0; nf < 4; nf++) {
            int col = bn + wn * 32 + nf * 8 + 2 * (lane & 3);
            if (OM == 1) {
                __half* C = (__half*)Cv;
                *(__half2*)(C + (size_t)row * ldc + col) =
                    __floats2half2_rn(acc[mf][nf][0], acc[mf][nf][1]);
                *(__half2*)(C + (size_t)(row + 8) * ldc + col) =
                    __floats2half2_rn(acc[mf][nf][2], acc[mf][nf][3]);
            } else if (OM == 2) {
                float* C = (float*)Cv;
                float b0 = bias[col], b1 = bias[col + 1];
                *(float2*)(C + (size_t)row * ldc + col) =
                    make_float2(sp_f(acc[mf][nf][0] + b0), sp_f(acc[mf][nf][1] + b1));
                *(float2*)(C + (size_t)(row + 8) * ldc + col) =
                    make_float2(sp_f(acc[mf][nf][2] + b0), sp_f(acc[mf][nf][3] + b1));
            } else {
                float* C = (float*)Cv;
                *(float2*)(C + (size_t)row * ldc + col) =
                    make_float2(acc[mf][nf][0], acc[mf][nf][1]);
                *(float2*)(C + (size_t)(row + 8) * ldc + col) =
                    make_float2(acc[mf][nf][2], acc[mf][nf][3]);
            }
        }
    }
}

// ---------------- gemm_w: 64x128, 4 warps (32x64), 3-stage, 3 CTAs/SM ---------
// Higher MMA:LDSM ratio (2.67) at 12 warps/SM. For head + in-proj.
#define STG_WA 8192      // A: 64 rows x 128B
#define STG_WB 16384     // B: 128 rows x 128B
#define SMEM_GW (3 * (STG_WA + STG_WB))  // 73728

template<int OM>   // 0 fp32 out, 1 half out
__global__ __launch_bounds__(128, 3)
void gemm_w(const __half* __restrict__ A, const __half* __restrict__ B,
            void* __restrict__ Cv, int K, int lda, int ldb, int ldc)
{
    extern __shared__ char smem[];
    const int tid = threadIdx.x, lane = tid & 31, wid = tid >> 5;
    const int wm = wid >> 1, wn = wid & 1;
    const int bm = blockIdx.x * 64, bn = blockIdx.y * 128;
    const int nc = K >> 6;
    const int lr = lane & 7, lg = lane >> 3;

    const uint32_t sb = smem_u32(smem);
    const __half* Ab = A + (size_t)bm * lda;
    const __half* Bb = B + (size_t)bn * ldb;

    auto loadA = [&](int chunk, int st) {
        uint32_t d0 = sb + st * (STG_WA + STG_WB);
        const __half* s0 = Ab + chunk * 64;
#pragma unroll
        for (int it = 0; it < 4; it++) {
            int i = tid + it * 128;
            int r = i >> 3, q = i & 7;
            uint32_t off = ((uint32_t)r << 7) | (((uint32_t)q << 4) ^ (((uint32_t)(r & 7)) << 4));
            CP_ASYNC16(d0 + off, s0 + (size_t)r * lda + q * 8);
        }
    };
    auto loadB = [&](int chunk, int st) {
        uint32_t d0 = sb + st * (STG_WA + STG_WB) + STG_WA;
        const __half* s0 = Bb + chunk * 64;
#pragma unroll
        for (int it = 0; it < 8; it++) {
            int i = tid + it * 128;
            int r = i >> 3, q = i & 7;
            uint32_t off = ((uint32_t)r << 7) | (((uint32_t)q << 4) ^ (((uint32_t)(r & 7)) << 4));
            CP_ASYNC16(d0 + off, s0 + (size_t)r * ldb + q * 8);
        }
    };

    const int a_row0 = wm * 32 + ((lg & 1) << 3) + lr;
    const int a_coff = (lg >> 1) << 4;
    const int b_row0 = wn * 64 + ((lg & 2) << 2) + lr;
    const int b_coff = (lg & 1) << 4;
    const uint32_t sw = (uint32_t)lr << 4;

    float acc[2][8][4];
#pragma unroll
    for (int i = 0; i < 2; i++)
#pragma unroll
        for (int j = 0; j < 8; j++)
#pragma unroll
            for (int v = 0; v < 4; v++) acc[i][j][v] = 0.0f;

    int npre = nc < 2 ? nc : 2;
    for (int c = 0; c < npre; c++) { loadA(c, c); loadB(c, c); CP_COMMIT(); }

    for (int i = 0; i < nc; i++) {
        if (i + 2 < nc) { CP_WAIT(1); } else { CP_WAIT(0); }
        __syncthreads();
        if (i + 2 < nc) {
            int s2 = (i + 2) % 3;
            loadA(i + 2, s2); loadB(i + 2, s2); CP_COMMIT();
        }
        uint32_t abase = sb + (i % 3) * (STG_WA + STG_WB);
        uint32_t bbase = abase + STG_WA;
#pragma unroll
        for (int ks = 0; ks < 4; ks++) {
            const uint32_t kb = (uint32_t)ks * 32;
            uint32_t afr[2][4];
#pragma unroll
            for (int mf = 0; mf < 2; mf++) {
                uint32_t ad = abase + (uint32_t)(a_row0 + mf * 16) * 128 + ((kb + a_coff) ^ sw);
                LDSM4(afr[mf][0], afr[mf][1], afr[mf][2], afr[mf][3], ad);
            }
            uint32_t bfr[8][2];
#pragma unroll
            for (int p = 0; p < 4; p++) {
                uint32_t bd = bbase + (uint32_t)(b_row0 + p * 16) * 128 + ((kb + b_coff) ^ sw);
                LDSM4(bfr[2 * p][0], bfr[2 * p][1], bfr[2 * p + 1][0], bfr[2 * p + 1][1], bd);
            }
#pragma unroll
            for (int mf = 0; mf < 2; mf++)
#pragma unroll
                for (int nf = 0; nf < 8; nf++)
                    mma_f16(acc[mf][nf], afr[mf], bfr[nf]);
        }
    }

#pragma unroll
    for (int mf = 0; mf < 2; mf++) {
        int row = bm + wm * 32 + mf * 16 + (lane >> 2);
#pragma unroll
        for (int nf = 0; nf < 8; nf++) {
            int col = bn + wn * 64 + nf * 8 + 2 * (lane & 3);
            if (OM == 1) {
                __half* C = (__half*)Cv;
                *(__half2*)(C + (size_t)row * ldc + col) =
                    __floats2half2_rn(acc[mf][nf][0], acc[mf][nf][1]);
                *(__half2*)(C + (size_t)(row + 8) * ldc + col) =
                    __floats2half2_rn(acc[mf][nf][2], acc[mf][nf][3]);
            } else {
                float* C = (float*)Cv;
                *(float2*)(C + (size_t)row * ldc + col) =
                    make_float2(acc[mf][nf][0], acc[mf][nf][1]);
                *(float2*)(C + (size_t)(row + 8) * ldc + col) =
                    make_float2(acc[mf][nf][2], acc[mf][nf][3]);
            }
        }
    }
}

// ---------------- elementwise / small kernels ----------------
__global__ void roundcopy_h(__half2* __restrict__ dst, const float4* __restrict__ src, int n4) {
    int i = blockIdx.x * blockDim.x + threadIdx.x;
    if (i < n4) {
        float4 v = src[i];
        dst[2 * i]     = __floats2half2_rn(v.x, v.y);
        dst[2 * i + 1] = __floats2half2_rn(v.z, v.w);
    }
}

__global__ void embed_kernel(const int* __restrict__ tokens,
                             const float* __restrict__ emb) {
    int i = blockIdx.x * blockDim.x + threadIdx.x;
    if (i < S_LEN * D_MODEL) {
        int l = i / D_MODEL, d = i - l * D_MODEL;
        float e = emb[(size_t)tokens[l] * D_MODEL + d];
        g_x[i]  = e;
        g_xh[i] = __float2half_rn(e);
    }
}

__global__ void padw_kernel(const float* __restrict__ xw, int L) {
    int i = blockIdx.x * 256 + threadIdx.x;
    if (i >= XDP * DI_) return;
    int row = i / DI_, col = i - row * DI_;
    g_wpad[L][i] = (row < 80) ? __float2half_rn(xw[((size_t)L * 80 + row) * DI_ + col])
                              : __half(0.0f);
}

__global__ void paddt_kernel(const float* __restrict__ dw, int L) {
    int i = blockIdx.x * 256 + threadIdx.x;
    if (i >= DI_ * 64) return;
    int row = i >> 6, col = i & 63;
    g_dtwpad[L][i] = (col < DTRANK) ? __float2half_rn(dw[((size_t)L * DI_ + row) * DTRANK + col])
                                    : __half(0.0f);
}

__global__ void conv_silu_kernel(const float* __restrict__ conv_w,
                                 const float* __restrict__ conv_b, int layer) {
    if (blockIdx.x == 0 && threadIdx.x == 0) atomicAdd(&g_epoch, 1);
    int i = blockIdx.x * blockDim.x + threadIdx.x;
    if (i >= S_LEN * DI_ / 2) return;
    int t = i / (DI_ / 2), cp = i - t * (DI_ / 2);
    int c = cp * 2;
    const float* w0 = conv_w + ((size_t)layer * DI_ + c) * K_CONV;
    const float* w1 = w0 + K_CONV;
    float a0 = conv_b[layer * DI_ + c];
    float a1 = conv_b[layer * DI_ + c + 1];
#pragma unroll
    for (int k = 0; k < K_CONV; k++) {
        int tt = t - (K_CONV - 1) + k;
        if (tt >= 0) {
            float2 xv = __half22float2(
                *(const __half2*)(g_xz + (size_t)tt * 2 * DI_ + c));
            a0 += w0[k] * xv.x;
            a1 += w1[k] * xv.y;
        }
    }
    *(__half2*)(g_xsh + (size_t)t * DI_ + c) =
        __floats2half2_rn(silu_f(a0), silu_f(a1));
}

// ---------------- single-pass scan with decoupled look-back -------------------
__global__ __launch_bounds__(128)
void scan_fused(const float* __restrict__ A_log, const float* __restrict__ Dp,
                int layer) {
    const int c = blockIdx.x * 128 + threadIdx.x;
    const int j = blockIdx.y;
    const int e2 = 2 * (*(volatile int*)&g_epoch);
    const int t0 = j * CLEN;

    float Acn[N_ST];
#pragma unroll
    for (int n = 0; n < N_ST; n++)
        Acn[n] = -expf(A_log[((size_t)layer * DI_ + c) * N_ST + n]);

    float h[N_ST];
#pragma unroll
    for (int n = 0; n < N_ST; n++) h[n] = 0.0f;
    float yloc[CLEN];
    float Sdt = 0.0f;
#pragma unroll 4
    for (int tt = 0; tt < CLEN; tt++) {
        int t = t0 + tt;
        float dtv = g_dtl[(size_t)t * DI_ + c];
        float xv  = __half2float(g_xsh[(size_t)t * DI_ + c]);
        float dx  = dtv * xv;
        Sdt += dtv;
        const __half2* bc = (const __half2*)(g_xdblh + (size_t)t * XDP + DTRANK);
        float y = 0.0f;
#pragma unroll
        for (int q = 0; q < 8; q++) {
            float2 B2 = __half22float2(bc[q]);
            float2 C2 = __half22float2(bc[8 + q]);
            float dA0 = __expf(dtv * Acn[2 * q]);
            float dA1 = __expf(dtv * Acn[2 * q + 1]);
            h[2 * q]     = dA0 * h[2 * q]     + dx * B2.x;
            h[2 * q + 1] = dA1 * h[2 * q + 1] + dx * B2.y;
            y += h[2 * q] * C2.x + h[2 * q + 1] * C2.y;
        }
        yloc[tt] = y;
    }

    float Pself[N_ST];
#pragma unroll
    for (int n = 0; n < N_ST; n++) Pself[n] = __expf(Sdt * Acn[n]);

    {
        float* Hp = g_H + (size_t)j * GROUPS + (size_t)c * N_ST;
        float* Pp = g_P + (size_t)j * GROUPS + (size_t)c * N_ST;
#pragma unroll
        for (int n = 0; n < N_ST; n++) { __stcg(&Hp[n], h[n]); __stcg(&Pp[n], Pself[n]); }
        __threadfence();
        ((volatile int*)g_flag)[j * DI_ + c] = e2 + 1;
    }

    float carry[N_ST];
#pragma unroll
    for (int n = 0; n < N_ST; n++) carry[n] = 0.0f;
    if (j > 0) {
        float prod[N_ST];
#pragma unroll
        for (int n = 0; n < N_ST; n++) prod[n] = 1.0f;
        int jj = j - 1;
        while (true) {
            int f = ((volatile int*)g_flag)[jj * DI_ + c];
            while (f < e2 + 1) {
                __nanosleep(60);
                f = ((volatile int*)g_flag)[jj * DI_ + c];
            }
            __threadfence();
            if (f >= e2 + 2) {
                const float* Iq = g_I + (size_t)jj * GROUPS + (size_t)c * N_ST;
#pragma unroll
                for (int n = 0; n < N_ST; n++) carry[n] += prod[n] * __ldcg(&Iq[n]);
                break;
            }
            const float* Hq = g_H + (size_t)jj * GROUPS + (size_t)c * N_ST;
            const float* Pq = g_P + (size_t)jj * GROUPS + (size_t)c * N_ST;
#pragma unroll
            for (int n = 0; n < N_ST; n++) {
                carry[n] += prod[n] * __ldcg(&Hq[n]);
                prod[n]  *= __ldcg(&Pq[n]);
            }
            if (--jj < 0) break;
        }
    }

    {
        float* Iq = g_I + (size_t)j * GROUPS + (size_t)c * N_ST;
#pragma unroll
        for (int n = 0; n < N_ST; n++) __stcg(&Iq[n], h[n] + Pself[n] * carry[n]);
        __threadfence();
        ((volatile int*)g_flag)[j * DI_ + c] = e2 + 2;
    }

    float Dpc = Dp[layer * DI_ + c];
    if (j == 0) {
#pragma unroll 4
        for (int tt = 0; tt < CLEN; tt++) {
            int t = t0 + tt;
            float xv = __half2float(g_xsh[(size_t)t * DI_ + c]);
            float z  = __half2float(g_xz[(size_t)t * 2 * DI_ + DI_ + c]);
            g_yh[(size_t)t * DI_ + c] = __float2half_rn(
                (yloc[tt] + xv * Dpc) * silu_f(z));
        }
    } else {
        float S = 0.0f;
#pragma unroll 4
        for (int tt = 0; tt < CLEN; tt++) {
            int t = t0 + tt;
            float dtv = g_dtl[(size_t)t * DI_ + c];
            S += dtv;
            const __half2* cc = (const __half2*)(g_xdblh + (size_t)t * XDP + DTRANK + N_ST);
            float v = 0.0f;
#pragma unroll
            for (int q = 0; q < 8; q++) {
                float2 C2 = __half22float2(cc[q]);
                v += C2.x * __expf(S * Acn[2 * q])     * carry[2 * q];
                v += C2.y * __expf(S * Acn[2 * q + 1]) * carry[2 * q + 1];
            }
            float xv = __half2float(g_xsh[(size_t)t * DI_ + c]);
            float z  = __half2float(g_xz[(size_t)t * 2 * DI_ + DI_ + c]);
            g_yh[(size_t)t * DI_ + c] = __float2half_rn(
                (yloc[tt] + v + xv * Dpc) * silu_f(z));
        }
    }
}

__global__ __launch_bounds__(256)
void ln_kernel(const float* __restrict__ gam, const float* __restrict__ bet, int layer) {
    int l = blockIdx.x;
    __shared__ float rsum[8], rsq[8];
    float sum = 0.0f, sq = 0.0f;
    for (int d = threadIdx.x; d < D_MODEL; d += 256) {
        float v = g_x[(size_t)l * D_MODEL + d] + g_tmp[(size_t)l * D_MODEL + d];
        sum += v; sq += v * v;
    }
#pragma unroll
    for (int o = 16; o > 0; o >>= 1) {
        sum += __shfl_down_sync(0xffffffffu, sum, o);
        sq  += __shfl_down_sync(0xffffffffu, sq, o);
    }
    int wid = threadIdx.x >> 5;
    if ((threadIdx.x & 31) == 0) { rsum[wid] = sum; rsq[wid] = sq; }
    __syncthreads();
    if (threadIdx.x == 0) {
        float s = 0.0f, q = 0.0f;
#pragma unroll
        for (int w = 0; w < 8; w++) { s += rsum[w]; q += rsq[w]; }
        rsum[0] = s; rsq[0] = q;
    }
    __syncthreads();
    float mu  = rsum[0] / (float)D_MODEL;
    float var = rsq[0] / (float)D_MODEL - mu * mu;
    float rinv = rsqrtf(var + 1e-5f);
    for (int d = threadIdx.x; d < D_MODEL; d += 256) {
        float v = g_x[(size_t)l * D_MODEL + d] + g_tmp[(size_t)l * D_MODEL + d];
        float o = (v - mu) * rinv * gam[layer * D_MODEL + d] + bet[layer * D_MODEL + d];
        g_x [(size_t)l * D_MODEL + d] = o;
        g_xh[(size_t)l * D_MODEL + d] = __float2half_rn(o);
    }
}

// ---------------- launch ----------------
extern "C" void kernel_launch(void* const* d_in, const int* in_sizes, int n_in,
                              void* d_out, int out_size) {
    const int*   tokens  = (const int*)  d_in[0];
    const float* emb     = (const float*)d_in[1];
    const float* in_w    = (const float*)d_in[2];
    const float* conv_w  = (const float*)d_in[3];
    const float* conv_b  = (const float*)d_in[4];
    const float* xproj_w = (const float*)d_in[5];
    const float* dt_w    = (const float*)d_in[6];
    const float* dt_b    = (const float*)d_in[7];
    const float* A_log   = (const float*)d_in[8];
    const float* Dp      = (const float*)d_in[9];
    const float* out_w   = (const float*)d_in[10];
    const float* ln_g    = (const float*)d_in[11];
    const float* ln_b    = (const float*)d_in[12];
    const float* head_w  = (const float*)d_in[13];
    float* out = (float*)d_out;

    static float *px = nullptr, *pdtl, *ptmp;
    static __half *pxh, *pxz, *pxsh, *pxdblh, *pyh, *pwh;
    static __half *pwpad[NL_], *pdtw[NL_], *pwbig[NL_], *pwout[NL_];
    static cudaStream_t s1;
    static cudaEvent_t evFork, evWh, evJoin;
    static cudaEvent_t evIn[NL_], evPP[NL_], evOw[NL_];
    if (!px) {
        cudaGetSymbolAddress((void**)&pxz,    g_xz);
        cudaGetSymbolAddress((void**)&pdtl,   g_dtl);
        cudaGetSymbolAddress((void**)&ptmp,   g_tmp);
        cudaGetSymbolAddress((void**)&pxh,    g_xh);
        cudaGetSymbolAddress((void**)&pxsh,   g_xsh);
        cudaGetSymbolAddress((void**)&pxdblh, g_xdblh);
        cudaGetSymbolAddress((void**)&pyh,    g_yh);
        cudaGetSymbolAddress((void**)&pwh,    g_wh);
        __half* hb;
        cudaGetSymbolAddress((void**)&hb, g_wpad);
        for (int L = 0; L < NL_; L++) pwpad[L] = hb + (size_t)L * XDP * DI_;
        cudaGetSymbolAddress((void**)&hb, g_dtwpad);
        for (int L = 0; L < NL_; L++) pdtw[L] = hb + (size_t)L * DI_ * 64;
        cudaGetSymbolAddress((void**)&hb, g_wbig);
        for (int L = 0; L < NL_; L++) pwbig[L] = hb + (size_t)L * 2 * DI_ * D_MODEL;
        cudaGetSymbolAddress((void**)&hb, g_wout);
        for (int L = 0; L < NL_; L++) pwout[L] = hb + (size_t)L * D_MODEL * DI_;
        cudaFuncSetAttribute(gemm_s<0>,
                             cudaFuncAttributeMaxDynamicSharedMemorySize, SMEM_GS);
        cudaFuncSetAttribute(gemm_s<1>,
                             cudaFuncAttributeMaxDynamicSharedMemorySize, SMEM_GS);
        cudaFuncSetAttribute(gemm_s<2>,
                             cudaFuncAttributeMaxDynamicSharedMemorySize, SMEM_GS);
        cudaFuncSetAttribute(gemm_w<0>,
                             cudaFuncAttributeMaxDynamicSharedMemorySize, SMEM_GW);
        cudaFuncSetAttribute(gemm_w<1>,
                             cudaFuncAttributeMaxDynamicSharedMemorySize, SMEM_GW);
        cudaStreamCreateWithFlags(&s1, cudaStreamNonBlocking);
        cudaEventCreateWithFlags(&evFork, cudaEventDisableTiming);
        cudaEventCreateWithFlags(&evWh,   cudaEventDisableTiming);
        cudaEventCreateWithFlags(&evJoin, cudaEventDisableTiming);
        for (int L = 0; L < NL_; L++) {
            cudaEventCreateWithFlags(&evIn[L], cudaEventDisableTiming);
            cudaEventCreateWithFlags(&evPP[L], cudaEventDisableTiming);
            cudaEventCreateWithFlags(&evOw[L], cudaEventDisableTiming);
        }
        cudaGetSymbolAddress((void**)&px, g_x);
    }

    cudaEventRecord(evFork, 0);
    cudaStreamWaitEvent(s1, evFork, 0);

    embed_kernel<<<(S_LEN * D_MODEL + 255) / 256, 256>>>(tokens, emb);          // idx 0

    roundcopy_h<<<(2 * DI_ * D_MODEL / 4 + 255) / 256, 256, 0, s1>>>(           // idx 1
        (__half2*)pwbig[0], (const float4*)in_w, 2 * DI_ * D_MODEL / 4);
    cudaEventRecord(evIn[0], s1);
    padw_kernel<<<(XDP * DI_ + 255) / 256, 256, 0, s1>>>(xproj_w, 0);           // idx 2

    // in-proj L0 (profiled launch idx 3): gemm_w 64x128 variant
    cudaStreamWaitEvent(0, evIn[0], 0);
    gemm_w<1><<<dim3(S_LEN / 64, 2 * DI_ / 128), 128, SMEM_GW>>>(
        pxh, pwbig[0], pxz, D_MODEL, D_MODEL, D_MODEL, 2 * DI_);                // idx 3

    paddt_kernel<<<(DI_ * 64 + 255) / 256, 256, 0, s1>>>(dt_w, 0);
    cudaEventRecord(evPP[0], s1);
    roundcopy_h<<<(D_MODEL * DI_ / 4 + 255) / 256, 256, 0, s1>>>(
        (__half2*)pwout[0], (const float4*)out_w, D_MODEL * DI_ / 4);
    cudaEventRecord(evOw[0], s1);
    roundcopy_h<<<(2 * DI_ * D_MODEL / 4 + 255) / 256, 256, 0, s1>>>(
        (__half2*)pwbig[1], (const float4*)(in_w + (size_t)2 * DI_ * D_MODEL),
        2 * DI_ * D_MODEL / 4);
    cudaEventRecord(evIn[1], s1);
    padw_kernel<<<(XDP * DI_ + 255) / 256, 256, 0, s1>>>(xproj_w, 1);
    paddt_kernel<<<(DI_ * 64 + 255) / 256, 256, 0, s1>>>(dt_w, 1);
    cudaEventRecord(evPP[1], s1);
    roundcopy_h<<<(D_MODEL * DI_ / 4 + 255) / 256, 256, 0, s1>>>(
        (__half2*)pwout[1], (const float4*)(out_w + (size_t)D_MODEL * DI_),
        D_MODEL * DI_ / 4);
    cudaEventRecord(evOw[1], s1);
    roundcopy_h<<<(VOCAB * D_MODEL / 4 + 255) / 256, 256, 0, s1>>>(
        (__half2*)pwh, (const float4*)head_w, VOCAB * D_MODEL / 4);
    cudaEventRecord(evWh, s1);
    cudaEventRecord(evJoin, s1);

    for (int L = 0; L < NL_; L++) {
        if (L > 0) {
            cudaStreamWaitEvent(0, evIn[L], 0);
            gemm_w<1><<<dim3(S_LEN / 64, 2 * DI_ / 128), 128, SMEM_GW>>>(
                pxh, pwbig[L], pxz, D_MODEL, D_MODEL, D_MODEL, 2 * DI_);
        }
        conv_silu_kernel<<<(S_LEN * DI_ / 2 + 255) / 256, 256>>>(conv_w, conv_b, L);

        cudaStreamWaitEvent(0, evPP[L], 0);
        gemm_s<1><<<dim3(S_LEN / 64, XDP / 64), 128, SMEM_GS>>>(
            pxsh, pwpad[L], pxdblh, DI_, DI_, DI_, XDP, nullptr);
        gemm_s<2><<<dim3(S_LEN / 64, DI_ / 64), 128, SMEM_GS>>>(
            pxdblh, pdtw[L], pdtl, 64, XDP, 64, DI_, dt_b + (size_t)L * DI_);

        scan_fused<<<dim3(DI_ / 128, NCHUNK), 128>>>(A_log, Dp, L);

        cudaStreamWaitEvent(0, evOw[L], 0);
        gemm_s<0><<<dim3(S_LEN / 64, D_MODEL / 64), 128, SMEM_GS>>>(
            pyh, pwout[L], ptmp, DI_, DI_, DI_, D_MODEL, nullptr);

        ln_kernel<<<S_LEN, 256>>>(ln_g, ln_b, L);
    }

    cudaStreamWaitEvent(0, evWh, 0);
    cudaStreamWaitEvent(0, evJoin, 0);
    gemm_w<0><<<dim3(S_LEN / 64, VOCAB / 128), 128, SMEM_GW>>>(
        pxh, pwh, out, D_MODEL, D_MODEL, D_MODEL, VOCAB);
}

// round 16
// speedup vs baseline: 1.1519x; 1.0059x over previous
#include <cuda_runtime.h>
#include <cuda_fp16.h>
#include <cstdint>
#include <math.h>

#define S_LEN   1024
#define D_MODEL 768
#define DI_     1536
#define N_ST    16
#define K_CONV  4
#define DTRANK  48
#define XDP     128
#define VOCAB   32000
#define NL_     2
#define NCHUNK  32
#define CLEN    32
#define GROUPS  (DI_ * N_ST)

#define GDC_WAIT() asm volatile("griddepcontrol.wait;" ::: "memory")

// ---------------- scratch ----------------
__device__ __align__(128) float  g_x    [S_LEN * D_MODEL];
__device__ __align__(128) __half g_xh   [S_LEN * D_MODEL];
__device__ __align__(128) __half g_xz   [S_LEN * 2 * DI_];
__device__ __align__(128) __half g_xsh  [S_LEN * DI_];
__device__ __align__(128) __half g_xdblh[S_LEN * XDP];
__device__ __align__(128) float  g_dtl  [S_LEN * DI_];
__device__ __align__(128) __half g_yh   [S_LEN * DI_];
__device__ __align__(128) float  g_tmp  [S_LEN * D_MODEL];
__device__ __align__(128) __half g_wpad  [NL_][XDP * DI_];
__device__ __align__(128) __half g_dtwpad[NL_][DI_ * 64];
__device__ __align__(128) __half g_wbig  [NL_][2 * DI_ * D_MODEL];
__device__ __align__(128) __half g_wout  [NL_][D_MODEL * DI_];
__device__ __align__(128) __half g_wh    [VOCAB * D_MODEL];
__device__ __align__(128) float  g_P  [NCHUNK * GROUPS];
__device__ __align__(128) float  g_H  [NCHUNK * GROUPS];
__device__ __align__(128) float  g_I  [NCHUNK * GROUPS];
__device__ int g_flag [NCHUNK * DI_];
__device__ int g_epoch;

// ---------------- helpers ----------------
__device__ __forceinline__ uint32_t smem_u32(const void* p) {
    uint32_t a;
    asm("{ .reg .u64 t; cvta.to.shared.u64 t, %1; cvt.u32.u64 %0, t; }" : "=r"(a) : "l"(p));
    return a;
}
__device__ __forceinline__ float silu_f(float x) { return x / (1.0f + __expf(-x)); }
__device__ __forceinline__ float sp_f(float a)   { return (a > 20.0f) ? a : log1pf(__expf(a)); }

#define CP_ASYNC16(dst, src) \
    asm volatile("cp.async.cg.shared.global [%0], [%1], 16;" :: "r"(dst), "l"(src))
#define CP_COMMIT() asm volatile("cp.async.commit_group;" ::: "memory")
#define CP_WAIT(n)  asm volatile("cp.async.wait_group %0;" :: "n"(n) : "memory")
#define LDSM4(d0, d1, d2, d3, a) \
    asm volatile("ldmatrix.sync.aligned.m8n8.x4.shared.b16 {%0,%1,%2,%3}, [%4];" \
        : "=r"(d0), "=r"(d1), "=r"(d2), "=r"(d3) : "r"(a))

__device__ __forceinline__ void mma_f16(float* c, const uint32_t* a, const uint32_t* b) {
    asm volatile(
        "mma.sync.aligned.m16n8k16.row.col.f32.f16.f16.f32 "
        "{%0,%1,%2,%3}, {%4,%5,%6,%7}, {%8,%9}, {%0,%1,%2,%3};"
        : "+f"(c[0]), "+f"(c[1]), "+f"(c[2]), "+f"(c[3])
        : "r"(a[0]), "r"(a[1]), "r"(a[2]), "r"(a[3]), "r"(b[0]), "r"(b[1]));
}

// ---------------- gemm_s: 64x64, 4 warps (32x32), 3-stage, 4 CTAs/SM ----------
#define STG_S 8192
#define SMEM_GS (3 * 2 * STG_S)

template<int OM>   // 0 fp32 out, 1 half out, 2 fp32 softplus(acc+bias) out
__global__ __launch_bounds__(128, 4)
void gemm_s(const __half* __restrict__ A, const __half* __restrict__ B,
            void* __restrict__ Cv, int K, int lda, int ldb, int ldc,
            const float* __restrict__ bias)
{
    GDC_WAIT();
    extern __shared__ char smem[];
    const int tid = threadIdx.x, lane = tid & 31, wid = tid >> 5;
    const int wm = wid >> 1, wn = wid & 1;
    const int bm = blockIdx.x * 64, bn = blockIdx.y * 64;
    const int nc = K >> 6;
    const int lr = lane & 7, lg = lane >> 3;

    const uint32_t sb = smem_u32(smem);
    const __half* Ab = A + (size_t)bm * lda;
    const __half* Bb = B + (size_t)bn * ldb;

    auto loadA = [&](int chunk, int st) {
        uint32_t d0 = sb + st * (2 * STG_S);
        const __half* s0 = Ab + chunk * 64;
#pragma unroll
        for (int it = 0; it < 4; it++) {
            int i = tid + it * 128;
            int r = i >> 3, q = i & 7;
            uint32_t off = ((uint32_t)r << 7) | (((uint32_t)q << 4) ^ (((uint32_t)(r & 7)) << 4));
            CP_ASYNC16(d0 + off, s0 + (size_t)r * lda + q * 8);
        }
    };
    auto loadB = [&](int chunk, int st) {
        uint32_t d0 = sb + st * (2 * STG_S) + STG_S;
        const __half* s0 = Bb + chunk * 64;
#pragma unroll
        for (int it = 0; it < 4; it++) {
            int i = tid + it * 128;
            int r = i >> 3, q = i & 7;
            uint32_t off = ((uint32_t)r << 7) | (((uint32_t)q << 4) ^ (((uint32_t)(r & 7)) << 4));
            CP_ASYNC16(d0 + off, s0 + (size_t)r * ldb + q * 8);
        }
    };

    const int a_row0 = wm * 32 + ((lg & 1) << 3) + lr;
    const int a_coff = (lg >> 1) << 4;
    const int b_row0 = wn * 32 + ((lg & 2) << 2) + lr;
    const int b_coff = (lg & 1) << 4;
    const uint32_t sw = (uint32_t)lr << 4;

    float acc[2][4][4];
#pragma unroll
    for (int i = 0; i < 2; i++)
#pragma unroll
        for (int j = 0; j < 4; j++)
#pragma unroll
            for (int v = 0; v < 4; v++) acc[i][j][v] = 0.0f;

    int npre = nc < 2 ? nc : 2;
    for (int c = 0; c < npre; c++) { loadA(c, c); loadB(c, c); CP_COMMIT(); }

    for (int i = 0; i < nc; i++) {
        if (i + 2 < nc) { CP_WAIT(1); } else { CP_WAIT(0); }
        __syncthreads();
        if (i + 2 < nc) {
            int s2 = (i + 2) % 3;
            loadA(i + 2, s2); loadB(i + 2, s2); CP_COMMIT();
        }
        uint32_t abase = sb + (i % 3) * (2 * STG_S);
        uint32_t bbase = abase + STG_S;
#pragma unroll
        for (int ks = 0; ks < 4; ks++) {
            const uint32_t kb = (uint32_t)ks * 32;
            uint32_t afr[2][4];
#pragma unroll
            for (int mf = 0; mf < 2; mf++) {
                uint32_t ad = abase + (uint32_t)(a_row0 + mf * 16) * 128 + ((kb + a_coff) ^ sw);
                LDSM4(afr[mf][0], afr[mf][1], afr[mf][2], afr[mf][3], ad);
            }
            uint32_t bfr[4][2];
#pragma unroll
            for (int p = 0; p < 2; p++) {
                uint32_t bd = bbase + (uint32_t)(b_row0 + p * 16) * 128 + ((kb + b_coff) ^ sw);
                LDSM4(bfr[2 * p][0], bfr[2 * p][1], bfr[2 * p + 1][0], bfr[2 * p + 1][1], bd);
            }
#pragma unroll
            for (int mf = 0; mf < 2; mf++)
#pragma unroll
                for (int nf = 0; nf < 4; nf++)
                    mma_f16(acc[mf][nf], afr[mf], bfr[nf]);
        }
    }

#pragma unroll
    for (int mf = 0; mf < 2; mf++) {
        int row = bm + wm * 32 + mf * 16 + (lane >> 2);
#pragma unroll
        for (int nf = 0; nf < 4; nf++) {
            int col = bn + wn * 32 + nf * 8 + 2 * (lane & 3);
            if (OM == 1) {
                __half* C = (__half*)Cv;
                *(__half2*)(C + (size_t)row * ldc + col) =
                    __floats2half2_rn(acc[mf][nf][0], acc[mf][nf][1]);
                *(__half2*)(C + (size_t)(row + 8) * ldc + col) =
                    __floats2half2_rn(acc[mf][nf][2], acc[mf][nf][3]);
            } else if (OM == 2) {
                float* C = (float*)Cv;
                float b0 = bias[col], b1 = bias[col + 1];
                *(float2*)(C + (size_t)row * ldc + col) =
                    make_float2(sp_f(acc[mf][nf][0] + b0), sp_f(acc[mf][nf][1] + b1));
                *(float2*)(C + (size_t)(row + 8) * ldc + col) =
                    make_float2(sp_f(acc[mf][nf][2] + b0), sp_f(acc[mf][nf][3] + b1));
            } else {
                float* C = (float*)Cv;
                *(float2*)(C + (size_t)row * ldc + col) =
                    make_float2(acc[mf][nf][0], acc[mf][nf][1]);
                *(float2*)(C + (size_t)(row + 8) * ldc + col) =
                    make_float2(acc[mf][nf][2], acc[mf][nf][3]);
            }
        }
    }
}

// ---------------- gemm_w: 64x128, 4 warps (32x64), 3-stage, 3 CTAs/SM ---------
#define STG_WA 8192
#define STG_WB 16384
#define SMEM_GW (3 * (STG_WA + STG_WB))

template<int OM>   // 0 fp32 out, 1 half out
__global__ __launch_bounds__(128, 3)
void gemm_w(const __half* __restrict__ A, const __half* __restrict__ B,
            void* __restrict__ Cv, int K, int lda, int ldb, int ldc)
{
    GDC_WAIT();
    extern __shared__ char smem[];
    const int tid = threadIdx.x, lane = tid & 31, wid = tid >> 5;
    const int wm = wid >> 1, wn = wid & 1;
    const int bm = blockIdx.x * 64, bn = blockIdx.y * 128;
    const int nc = K >> 6;
    const int lr = lane & 7, lg = lane >> 3;

    const uint32_t sb = smem_u32(smem);
    const __half* Ab = A + (size_t)bm * lda;
    const __half* Bb = B + (size_t)bn * ldb;

    auto loadA = [&](int chunk, int st) {
        uint32_t d0 = sb + st * (STG_WA + STG_WB);
        const __half* s0 = Ab + chunk * 64;
#pragma unroll
        for (int it = 0; it < 4; it++) {
            int i = tid + it * 128;
            int r = i >> 3, q = i & 7;
            uint32_t off = ((uint32_t)r << 7) | (((uint32_t)q << 4) ^ (((uint32_t)(r & 7)) << 4));
            CP_ASYNC16(d0 + off, s0 + (size_t)r * lda + q * 8);
        }
    };
    auto loadB = [&](int chunk, int st) {
        uint32_t d0 = sb + st * (STG_WA + STG_WB) + STG_WA;
        const __half* s0 = Bb + chunk * 64;
#pragma unroll
        for (int it = 0; it < 8; it++) {
            int i = tid + it * 128;
            int r = i >> 3, q = i & 7;
            uint32_t off = ((uint32_t)r << 7) | (((uint32_t)q << 4) ^ (((uint32_t)(r & 7)) << 4));
            CP_ASYNC16(d0 + off, s0 + (size_t)r * ldb + q * 8);
        }
    };

    const int a_row0 = wm * 32 + ((lg & 1) << 3) + lr;
    const int a_coff = (lg >> 1) << 4;
    const int b_row0 = wn * 64 + ((lg & 2) << 2) + lr;
    const int b_coff = (lg & 1) << 4;
    const uint32_t sw = (uint32_t)lr << 4;

    float acc[2][8][4];
#pragma unroll
    for (int i = 0; i < 2; i++)
#pragma unroll
        for (int j = 0; j < 8; j++)
#pragma unroll
            for (int v = 0; v < 4; v++) acc[i][j][v] = 0.0f;

    int npre = nc < 2 ? nc : 2;
    for (int c = 0; c < npre; c++) { loadA(c, c); loadB(c, c); CP_COMMIT(); }

    for (int i = 0; i < nc; i++) {
        if (i + 2 < nc) { CP_WAIT(1); } else { CP_WAIT(0); }
        __syncthreads();
        if (i + 2 < nc) {
            int s2 = (i + 2) % 3;
            loadA(i + 2, s2); loadB(i + 2, s2); CP_COMMIT();
        }
        uint32_t abase = sb + (i % 3) * (STG_WA + STG_WB);
        uint32_t bbase = abase + STG_WA;
#pragma unroll
        for (int ks = 0; ks < 4; ks++) {
            const uint32_t kb = (uint32_t)ks * 32;
            uint32_t afr[2][4];
#pragma unroll
            for (int mf = 0; mf < 2; mf++) {
                uint32_t ad = abase + (uint32_t)(a_row0 + mf * 16) * 128 + ((kb + a_coff) ^ sw);
                LDSM4(afr[mf][0], afr[mf][1], afr[mf][2], afr[mf][3], ad);
            }
            uint32_t bfr[8][2];
#pragma unroll
            for (int p = 0; p < 4; p++) {
                uint32_t bd = bbase + (uint32_t)(b_row0 + p * 16) * 128 + ((kb + b_coff) ^ sw);
                LDSM4(bfr[2 * p][0], bfr[2 * p][1], bfr[2 * p + 1][0], bfr[2 * p + 1][1], bd);
            }
#pragma unroll
            for (int mf = 0; mf < 2; mf++)
#pragma unroll
                for (int nf = 0; nf < 8; nf++)
                    mma_f16(acc[mf][nf], afr[mf], bfr[nf]);
        }
    }

#pragma unroll
    for (int mf = 0; mf < 2; mf++) {
        int row = bm + wm * 32 + mf * 16 + (lane >> 2);
#pragma unroll
        for (int nf = 0; nf < 8; nf++) {
            int col = bn + wn * 64 + nf * 8 + 2 * (lane & 3);
            if (OM == 1) {
                __half* C = (__half*)Cv;
                *(__half2*)(C + (size_t)row * ldc + col) =
                    __floats2half2_rn(acc[mf][nf][0], acc[mf][nf][1]);
                *(__half2*)(C + (size_t)(row + 8) * ldc + col) =
                    __floats2half2_rn(acc[mf][nf][2], acc[mf][nf][3]);
            } else {
                float* C = (float*)Cv;
                *(float2*)(C + (size_t)row * ldc + col) =
                    make_float2(acc[mf][nf][0], acc[mf][nf][1]);
                *(float2*)(C + (size_t)(row + 8) * ldc + col) =
                    make_float2(acc[mf][nf][2], acc[mf][nf][3]);
            }
        }
    }
}

// ---------------- elementwise / small kernels ----------------
__global__ void roundcopy_h(__half2* __restrict__ dst, const float4* __restrict__ src, int n4) {
    int i = blockIdx.x * blockDim.x + threadIdx.x;
    if (i < n4) {
        float4 v = src[i];
        dst[2 * i]     = __floats2half2_rn(v.x, v.y);
        dst[2 * i + 1] = __floats2half2_rn(v.z, v.w);
    }
}

__global__ void embed_kernel(const int* __restrict__ tokens,
                             const float* __restrict__ emb) {
    int i = blockIdx.x * blockDim.x + threadIdx.x;
    if (i < S_LEN * D_MODEL) {
        int l = i / D_MODEL, d = i - l * D_MODEL;
        float e = emb[(size_t)tokens[l] * D_MODEL + d];
        g_x[i]  = e;
        g_xh[i] = __float2half_rn(e);
    }
}

__global__ void padw_kernel(const float* __restrict__ xw, int L) {
    int i = blockIdx.x * 256 + threadIdx.x;
    if (i >= XDP * DI_) return;
    int row = i / DI_, col = i - row * DI_;
    g_wpad[L][i] = (row < 80) ? __float2half_rn(xw[((size_t)L * 80 + row) * DI_ + col])
                              : __half(0.0f);
}

__global__ void paddt_kernel(const float* __restrict__ dw, int L) {
    int i = blockIdx.x * 256 + threadIdx.x;
    if (i >= DI_ * 64) return;
    int row = i >> 6, col = i & 63;
    g_dtwpad[L][i] = (col < DTRANK) ? __float2half_rn(dw[((size_t)L * DI_ + row) * DTRANK + col])
                                    : __half(0.0f);
}

__global__ void conv_silu_kernel(const float* __restrict__ conv_w,
                                 const float* __restrict__ conv_b, int layer) {
    GDC_WAIT();
    if (blockIdx.x == 0 && threadIdx.x == 0) atomicAdd(&g_epoch, 1);
    int i = blockIdx.x * blockDim.x + threadIdx.x;
    if (i >= S_LEN * DI_ / 2) return;
    int t = i / (DI_ / 2), cp = i - t * (DI_ / 2);
    int c = cp * 2;
    const float* w0 = conv_w + ((size_t)layer * DI_ + c) * K_CONV;
    const float* w1 = w0 + K_CONV;
    float a0 = conv_b[layer * DI_ + c];
    float a1 = conv_b[layer * DI_ + c + 1];
#pragma unroll
    for (int k = 0; k < K_CONV; k++) {
        int tt = t - (K_CONV - 1) + k;
        if (tt >= 0) {
            float2 xv = __half22float2(
                *(const __half2*)(g_xz + (size_t)tt * 2 * DI_ + c));
            a0 += w0[k] * xv.x;
            a1 += w1[k] * xv.y;
        }
    }
    *(__half2*)(g_xsh + (size_t)t * DI_ + c) =
        __floats2half2_rn(silu_f(a0), silu_f(a1));
}

// ---------------- single-pass scan with decoupled look-back -------------------
__global__ __launch_bounds__(128)
void scan_fused(const float* __restrict__ A_log, const float* __restrict__ Dp,
                int layer) {
    GDC_WAIT();
    const int c = blockIdx.x * 128 + threadIdx.x;
    const int j = blockIdx.y;
    const int e2 = 2 * (*(volatile int*)&g_epoch);
    const int t0 = j * CLEN;

    float Acn[N_ST];
#pragma unroll
    for (int n = 0; n < N_ST; n++)
        Acn[n] = -expf(A_log[((size_t)layer * DI_ + c) * N_ST + n]);

    float h[N_ST];
#pragma unroll
    for (int n = 0; n < N_ST; n++) h[n] = 0.0f;
    float yloc[CLEN];
    float Sdt = 0.0f;
#pragma unroll 4
    for (int tt = 0; tt < CLEN; tt++) {
        int t = t0 + tt;
        float dtv = g_dtl[(size_t)t * DI_ + c];
        float xv  = __half2float(g_xsh[(size_t)t * DI_ + c]);
        float dx  = dtv * xv;
        Sdt += dtv;
        const __half2* bc = (const __half2*)(g_xdblh + (size_t)t * XDP + DTRANK);
        float y = 0.0f;
#pragma unroll
        for (int q = 0; q < 8; q++) {
            float2 B2 = __half22float2(bc[q]);
            float2 C2 = __half22float2(bc[8 + q]);
            float dA0 = __expf(dtv * Acn[2 * q]);
            float dA1 = __expf(dtv * Acn[2 * q + 1]);
            h[2 * q]     = dA0 * h[2 * q]     + dx * B2.x;
            h[2 * q + 1] = dA1 * h[2 * q + 1] + dx * B2.y;
            y += h[2 * q] * C2.x + h[2 * q + 1] * C2.y;
        }
        yloc[tt] = y;
    }

    float Pself[N_ST];
#pragma unroll
    for (int n = 0; n < N_ST; n++) Pself[n] = __expf(Sdt * Acn[n]);

    {
        float* Hp = g_H + (size_t)j * GROUPS + (size_t)c * N_ST;
        float* Pp = g_P + (size_t)j * GROUPS + (size_t)c * N_ST;
#pragma unroll
        for (int n = 0; n < N_ST; n++) { __stcg(&Hp[n], h[n]); __stcg(&Pp[n], Pself[n]); }
        __threadfence();
        ((volatile int*)g_flag)[j * DI_ + c] = e2 + 1;
    }

    float carry[N_ST];
#pragma unroll
    for (int n = 0; n < N_ST; n++) carry[n] = 0.0f;
    if (j > 0) {
        float prod[N_ST];
#pragma unroll
        for (int n = 0; n < N_ST; n++) prod[n] = 1.0f;
        int jj = j - 1;
        while (true) {
            int f = ((volatile int*)g_flag)[jj * DI_ + c];
            while (f < e2 + 1) {
                __nanosleep(60);
                f = ((volatile int*)g_flag)[jj * DI_ + c];
            }
            __threadfence();
            if (f >= e2 + 2) {
                const float* Iq = g_I + (size_t)jj * GROUPS + (size_t)c * N_ST;
#pragma unroll
                for (int n = 0; n < N_ST; n++) carry[n] += prod[n] * __ldcg(&Iq[n]);
                break;
            }
            const float* Hq = g_H + (size_t)jj * GROUPS + (size_t)c * N_ST;
            const float* Pq = g_P + (size_t)jj * GROUPS + (size_t)c * N_ST;
#pragma unroll
            for (int n = 0; n < N_ST; n++) {
                carry[n] += prod[n] * __ldcg(&Hq[n]);
                prod[n]  *= __ldcg(&Pq[n]);
            }
            if (--jj < 0) break;
        }
    }

    {
        float* Iq = g_I + (size_t)j * GROUPS + (size_t)c * N_ST;
#pragma unroll
        for (int n = 0; n < N_ST; n++) __stcg(&Iq[n], h[n] + Pself[n] * carry[n]);
        __threadfence();
        ((volatile int*)g_flag)[j * DI_ + c] = e2 + 2;
    }

    float Dpc = Dp[layer * DI_ + c];
    if (j == 0) {
#pragma unroll 4
        for (int tt = 0; tt < CLEN; tt++) {
            int t = t0 + tt;
            float xv = __half2float(g_xsh[(size_t)t * DI_ + c]);
            float z  = __half2float(g_xz[(size_t)t * 2 * DI_ + DI_ + c]);
            g_yh[(size_t)t * DI_ + c] = __float2half_rn(
                (yloc[tt] + xv * Dpc) * silu_f(z));
        }
    } else {
        float S = 0.0f;
#pragma unroll 4
        for (int tt = 0; tt < CLEN; tt++) {
            int t = t0 + tt;
            float dtv = g_dtl[(size_t)t * DI_ + c];
            S += dtv;
            const __half2* cc = (const __half2*)(g_xdblh + (size_t)t * XDP + DTRANK + N_ST);
            float v = 0.0f;
#pragma unroll
            for (int q = 0; q < 8; q++) {
                float2 C2 = __half22float2(cc[q]);
                v += C2.x * __expf(S * Acn[2 * q])     * carry[2 * q];
                v += C2.y * __expf(S * Acn[2 * q + 1]) * carry[2 * q + 1];
            }
            float xv = __half2float(g_xsh[(size_t)t * DI_ + c]);
            float z  = __half2float(g_xz[(size_t)t * 2 * DI_ + DI_ + c]);
            g_yh[(size_t)t * DI_ + c] = __float2half_rn(
                (yloc[tt] + v + xv * Dpc) * silu_f(z));
        }
    }
}

__global__ __launch_bounds__(256)
void ln_kernel(const float* __restrict__ gam, const float* __restrict__ bet, int layer) {
    GDC_WAIT();
    int l = blockIdx.x;
    __shared__ float rsum[8], rsq[8];
    float sum = 0.0f, sq = 0.0f;
    for (int d = threadIdx.x; d < D_MODEL; d += 256) {
        float v = g_x[(size_t)l * D_MODEL + d] + g_tmp[(size_t)l * D_MODEL + d];
        sum += v; sq += v * v;
    }
#pragma unroll
    for (int o = 16; o > 0; o >>= 1) {
        sum += __shfl_down_sync(0xffffffffu, sum, o);
        sq  += __shfl_down_sync(0xffffffffu, sq, o);
    }
    int wid = threadIdx.x >> 5;
    if ((threadIdx.x & 31) == 0) { rsum[wid] = sum; rsq[wid] = sq; }
    __syncthreads();
    if (threadIdx.x == 0) {
        float s = 0.0f, q = 0.0f;
#pragma unroll
        for (int w = 0; w < 8; w++) { s += rsum[w]; q += rsq[w]; }
        rsum[0] = s; rsq[0] = q;
    }
    __syncthreads();
    float mu  = rsum[0] / (float)D_MODEL;
    float var = rsq[0] / (float)D_MODEL - mu * mu;
    float rinv = rsqrtf(var + 1e-5f);
    for (int d = threadIdx.x; d < D_MODEL; d += 256) {
        float v = g_x[(size_t)l * D_MODEL + d] + g_tmp[(size_t)l * D_MODEL + d];
        float o = (v - mu) * rinv * gam[layer * D_MODEL + d] + bet[layer * D_MODEL + d];
        g_x [(size_t)l * D_MODEL + d] = o;
        g_xh[(size_t)l * D_MODEL + d] = __float2half_rn(o);
    }
}

// ---------------- PDL launcher ----------------
template<typename Kern, typename... Args>
static inline void launch_pdl(Kern k, dim3 g, dim3 b, size_t smem, cudaStream_t s,
                              Args... args) {
    cudaLaunchConfig_t cfg = {};
    cfg.gridDim = g; cfg.blockDim = b; cfg.dynamicSmemBytes = smem; cfg.stream = s;
    cudaLaunchAttribute at[1];
    at[0].id = cudaLaunchAttributeProgrammaticStreamSerialization;
    at[0].val.programmaticStreamSerializationAllowed = 1;
    cfg.attrs = at; cfg.numAttrs = 1;
    cudaLaunchKernelEx(&cfg, k, args...);
}

// ---------------- launch ----------------
extern "C" void kernel_launch(void* const* d_in, const int* in_sizes, int n_in,
                              void* d_out, int out_size) {
    const int*   tokens  = (const int*)  d_in[0];
    const float* emb     = (const float*)d_in[1];
    const float* in_w    = (const float*)d_in[2];
    const float* conv_w  = (const float*)d_in[3];
    const float* conv_b  = (const float*)d_in[4];
    const float* xproj_w = (const float*)d_in[5];
    const float* dt_w    = (const float*)d_in[6];
    const float* dt_b    = (const float*)d_in[7];
    const float* A_log   = (const float*)d_in[8];
    const float* Dp      = (const float*)d_in[9];
    const float* out_w   = (const float*)d_in[10];
    const float* ln_g    = (const float*)d_in[11];
    const float* ln_b    = (const float*)d_in[12];
    const float* head_w  = (const float*)d_in[13];
    float* out = (float*)d_out;

    static float *px = nullptr, *pdtl, *ptmp;
    static __half *pxh, *pxz, *pxsh, *pxdblh, *pyh, *pwh;
    static __half *pwpad[NL_], *pdtw[NL_], *pwbig[NL_], *pwout[NL_];
    static cudaStream_t s1;
    static cudaEvent_t evFork, evWh, evJoin;
    static cudaEvent_t evIn[NL_], evPP[NL_], evOw[NL_];
    if (!px) {
        cudaGetSymbolAddress((void**)&pxz,    g_xz);
        cudaGetSymbolAddress((void**)&pdtl,   g_dtl);
        cudaGetSymbolAddress((void**)&ptmp,   g_tmp);
        cudaGetSymbolAddress((void**)&pxh,    g_xh);
        cudaGetSymbolAddress((void**)&pxsh,   g_xsh);
        cudaGetSymbolAddress((void**)&pxdblh, g_xdblh);
        cudaGetSymbolAddress((void**)&pyh,    g_yh);
        cudaGetSymbolAddress((void**)&pwh,    g_wh);
        __half* hb;
        cudaGetSymbolAddress((void**)&hb, g_wpad);
        for (int L = 0; L < NL_; L++) pwpad[L] = hb + (size_t)L * XDP * DI_;
        cudaGetSymbolAddress((void**)&hb, g_dtwpad);
        for (int L = 0; L < NL_; L++) pdtw[L] = hb + (size_t)L * DI_ * 64;
        cudaGetSymbolAddress((void**)&hb, g_wbig);
        for (int L = 0; L < NL_; L++) pwbig[L] = hb + (size_t)L * 2 * DI_ * D_MODEL;
        cudaGetSymbolAddress((void**)&hb, g_wout);
        for (int L = 0; L < NL_; L++) pwout[L] = hb + (size_t)L * D_MODEL * DI_;
        cudaFuncSetAttribute(gemm_s<0>,
                             cudaFuncAttributeMaxDynamicSharedMemorySize, SMEM_GS);
        cudaFuncSetAttribute(gemm_s<1>,
                             cudaFuncAttributeMaxDynamicSharedMemorySize, SMEM_GS);
        cudaFuncSetAttribute(gemm_s<2>,
                             cudaFuncAttributeMaxDynamicSharedMemorySize, SMEM_GS);
        cudaFuncSetAttribute(gemm_w<0>,
                             cudaFuncAttributeMaxDynamicSharedMemorySize, SMEM_GW);
        cudaFuncSetAttribute(gemm_w<1>,
                             cudaFuncAttributeMaxDynamicSharedMemorySize, SMEM_GW);
        cudaStreamCreateWithFlags(&s1, cudaStreamNonBlocking);
        cudaEventCreateWithFlags(&evFork, cudaEventDisableTiming);
        cudaEventCreateWithFlags(&evWh,   cudaEventDisableTiming);
        cudaEventCreateWithFlags(&evJoin, cudaEventDisableTiming);
        for (int L = 0; L < NL_; L++) {
            cudaEventCreateWithFlags(&evIn[L], cudaEventDisableTiming);
            cudaEventCreateWithFlags(&evPP[L], cudaEventDisableTiming);
            cudaEventCreateWithFlags(&evOw[L], cudaEventDisableTiming);
        }
        cudaGetSymbolAddress((void**)&px, g_x);
    }

    cudaEventRecord(evFork, 0);
    cudaStreamWaitEvent(s1, evFork, 0);

    embed_kernel<<<(S_LEN * D_MODEL + 255) / 256, 256>>>(tokens, emb);          // idx 0

    roundcopy_h<<<(2 * DI_ * D_MODEL / 4 + 255) / 256, 256, 0, s1>>>(           // idx 1
        (__half2*)pwbig[0], (const float4*)in_w, 2 * DI_ * D_MODEL / 4);
    cudaEventRecord(evIn[0], s1);
    padw_kernel<<<(XDP * DI_ + 255) / 256, 256, 0, s1>>>(xproj_w, 0);           // idx 2

    // in-proj L0 (profiled launch idx 3)
    cudaStreamWaitEvent(0, evIn[0], 0);
    launch_pdl(gemm_w<1>, dim3(S_LEN / 64, 2 * DI_ / 128), dim3(128), SMEM_GW,
               (cudaStream_t)0, pxh, (const __half*)pwbig[0], (void*)pxz,
               D_MODEL, D_MODEL, D_MODEL, 2 * DI_);                             // idx 3

    paddt_kernel<<<(DI_ * 64 + 255) / 256, 256, 0, s1>>>(dt_w, 0);
    cudaEventRecord(evPP[0], s1);
    roundcopy_h<<<(D_MODEL * DI_ / 4 + 255) / 256, 256, 0, s1>>>(
        (__half2*)pwout[0], (const float4*)out_w, D_MODEL * DI_ / 4);
    cudaEventRecord(evOw[0], s1);
    roundcopy_h<<<(2 * DI_ * D_MODEL / 4 + 255) / 256, 256, 0, s1>>>(
        (__half2*)pwbig[1], (const float4*)(in_w + (size_t)2 * DI_ * D_MODEL),
        2 * DI_ * D_MODEL / 4);
    cudaEventRecord(evIn[1], s1);
    padw_kernel<<<(XDP * DI_ + 255) / 256, 256, 0, s1>>>(xproj_w, 1);
    paddt_kernel<<<(DI_ * 64 + 255) / 256, 256, 0, s1>>>(dt_w, 1);
    cudaEventRecord(evPP[1], s1);
    roundcopy_h<<<(D_MODEL * DI_ / 4 + 255) / 256, 256, 0, s1>>>(
        (__half2*)pwout[1], (const float4*)(out_w + (size_t)D_MODEL * DI_),
        D_MODEL * DI_ / 4);
    cudaEventRecord(evOw[1], s1);
    roundcopy_h<<<(VOCAB * D_MODEL / 4 + 255) / 256, 256, 0, s1>>>(
        (__half2*)pwh, (const float4*)head_w, VOCAB * D_MODEL / 4);
    cudaEventRecord(evWh, s1);
    cudaEventRecord(evJoin, s1);

    for (int L = 0; L < NL_; L++) {
        if (L > 0) {
            cudaStreamWaitEvent(0, evIn[L], 0);
            launch_pdl(gemm_w<1>, dim3(S_LEN / 64, 2 * DI_ / 128), dim3(128), SMEM_GW,
                       (cudaStream_t)0, pxh, (const __half*)pwbig[L], (void*)pxz,
                       D_MODEL, D_MODEL, D_MODEL, 2 * DI_);
        }
        launch_pdl(conv_silu_kernel, dim3((S_LEN * DI_ / 2 + 255) / 256), dim3(256), 0,
                   (cudaStream_t)0, conv_w, conv_b, L);

        cudaStreamWaitEvent(0, evPP[L], 0);
        launch_pdl(gemm_s<1>, dim3(S_LEN / 64, XDP / 64), dim3(128), SMEM_GS,
                   (cudaStream_t)0, pxsh, (const __half*)pwpad[L], (void*)pxdblh,
                   DI_, DI_, DI_, XDP, (const float*)nullptr);
        launch_pdl(gemm_s<2>, dim3(S_LEN / 64, DI_ / 64), dim3(128), SMEM_GS,
                   (cudaStream_t)0, pxdblh, (const __half*)pdtw[L], (void*)pdtl,
                   64, XDP, 64, DI_, (const float*)(dt_b + (size_t)L * DI_));

        launch_pdl(scan_fused, dim3(DI_ / 128, NCHUNK), dim3(128), 0,
                   (cudaStream_t)0, A_log, Dp, L);

        cudaStreamWaitEvent(0, evOw[L], 0);
        launch_pdl(gemm_s<0>, dim3(S_LEN / 64, D_MODEL / 64), dim3(128), SMEM_GS,
                   (cudaStream_t)0, pyh, (const __half*)pwout[L], (void*)ptmp,
                   DI_, DI_, DI_, D_MODEL, (const float*)nullptr);

        launch_pdl(ln_kernel, dim3(S_LEN), dim3(256), 0,
                   (cudaStream_t)0, ln_g, ln_b, L);
    }

    cudaStreamWaitEvent(0, evWh, 0);
    cudaStreamWaitEvent(0, evJoin, 0);
    launch_pdl(gemm_w<0>, dim3(S_LEN / 64, VOCAB / 128), dim3(128), SMEM_GW,
               (cudaStream_t)0, pxh, (const __half*)pwh, (void*)out,
               D_MODEL, D_MODEL, D_MODEL, VOCAB);
}